// round 1
// baseline (speedup 1.0000x reference)
#include <cuda_runtime.h>

#define NMAX 100000
#define EMAX 1600000
#define D    128

// ---------------- scratch (static device allocations) ----------------
__device__ float g_p [NMAX * D];   // p[v] = sigmoid(f_dst@wr + h@ur + br) * h
__device__ float g_zp[NMAX * D];   // f_src@wz + bz
__device__ float g_cp[NMAX * D];   // f_src@w  + b
__device__ float g_s [NMAX * D];   // segment_sum(h[src], dst)
__device__ float g_q [NMAX * D];   // segment_sum(p[src], dst)
__device__ int   g_cnt[NMAX];
__device__ int   g_off[NMAX + 1];
__device__ int   g_cur[NMAX];
__device__ int   g_perm[EMAX];

typedef unsigned long long u64;

// ---------------- f32x2 packed-FMA helpers (FFMA2 in SASS) ----------------
__device__ __forceinline__ u64 dup2(float x) {
    u64 r; asm("mov.b64 %0,{%1,%1};" : "=l"(r) : "f"(x)); return r;
}
__device__ __forceinline__ void fma2(u64 &acc, u64 a, u64 b) {
    asm("fma.rn.f32x2 %0,%1,%2,%0;" : "+l"(acc) : "l"(a), "l"(b));
}
__device__ __forceinline__ float2 unpack2(u64 v) {
    float2 r; asm("mov.b64 {%0,%1},%2;" : "=f"(r.x), "=f"(r.y) : "l"(v)); return r;
}
__device__ __forceinline__ float sigmoidf(float x) { return 1.0f / (1.0f + __expf(-x)); }

// ---------------- CSR build ----------------
__global__ void k_zero(int n) {
    int i = blockIdx.x * blockDim.x + threadIdx.x;
    if (i < n) g_cnt[i] = 0;
}

__global__ void k_hist(const int* __restrict__ dst, int e) {
    int i = blockIdx.x * blockDim.x + threadIdx.x;
    if (i < e) atomicAdd(&g_cnt[dst[i]], 1);
}

__global__ void k_scan(int n, int e) {
    __shared__ int sm[1024];
    int t = threadIdx.x;
    int CH = (n + 1023) >> 10;
    int base = t * CH;
    int sum = 0;
    for (int i = 0; i < CH; i++) {
        int idx = base + i;
        if (idx < n) sum += g_cnt[idx];
    }
    sm[t] = sum;
    __syncthreads();
    for (int off = 1; off < 1024; off <<= 1) {
        int v = (t >= off) ? sm[t - off] : 0;
        __syncthreads();
        sm[t] += v;
        __syncthreads();
    }
    int run = sm[t] - sum;  // exclusive prefix for this chunk
    for (int i = 0; i < CH; i++) {
        int idx = base + i;
        if (idx < n) {
            g_off[idx] = run;
            g_cur[idx] = run;
            run += g_cnt[idx];
        }
    }
    if (t == 0) g_off[n] = e;
}

__global__ void k_scatter(const int* __restrict__ src, const int* __restrict__ dst, int e) {
    int i = blockIdx.x * blockDim.x + threadIdx.x;
    if (i < e) {
        int d = dst[i];
        int pos = atomicAdd(&g_cur[d], 1);
        g_perm[pos] = src[i];
    }
}

// ---------------- segment reduce: warp per node ----------------
__global__ void k_reduce(const float* __restrict__ h, int n) {
    int gw = (blockIdx.x * blockDim.x + threadIdx.x) >> 5;
    int lane = threadIdx.x & 31;
    if (gw >= n) return;
    int i0 = g_off[gw], i1 = g_off[gw + 1];
    const float4* h4 = (const float4*)h;
    const float4* p4 = (const float4*)g_p;
    float4 sa = make_float4(0.f, 0.f, 0.f, 0.f);
    float4 qa = make_float4(0.f, 0.f, 0.f, 0.f);
    int i = i0;
    for (; i + 1 < i1; i += 2) {
        int u0 = g_perm[i], u1 = g_perm[i + 1];
        float4 a0 = h4[u0 * 32 + lane];
        float4 b0 = p4[u0 * 32 + lane];
        float4 a1 = h4[u1 * 32 + lane];
        float4 b1 = p4[u1 * 32 + lane];
        sa.x += a0.x + a1.x; sa.y += a0.y + a1.y; sa.z += a0.z + a1.z; sa.w += a0.w + a1.w;
        qa.x += b0.x + b1.x; qa.y += b0.y + b1.y; qa.z += b0.z + b1.z; qa.w += b0.w + b1.w;
    }
    if (i < i1) {
        int u0 = g_perm[i];
        float4 a0 = h4[u0 * 32 + lane];
        float4 b0 = p4[u0 * 32 + lane];
        sa.x += a0.x; sa.y += a0.y; sa.z += a0.z; sa.w += a0.w;
        qa.x += b0.x; qa.y += b0.y; qa.z += b0.z; qa.w += b0.w;
    }
    ((float4*)g_s)[gw * 32 + lane] = sa;
    ((float4*)g_q)[gw * 32 + lane] = qa;
}

// ---------------- GEMM tiling common constants ----------------
// block = 256 threads = 8 warps; warp (cs = w&3, rg = w>>2)
// lane: tx = lane&3 (col chunk within 32-col slice), ry = lane>>2 (row within 8)
// thread covers 8 output columns: colBase = cs*32 + tx*8 (4 float2 accumulators/matrix)
// one pass = 16 rows; smem W packed as float2 (u64), conflict-free LDS.128 pattern.
#define XPITCH 132
#define GEMM_SMEM (2 * 8192 * 8 + 2 * 64 * XPITCH * 4)   // 131072 + 67584 = 198656

// zpart = f_src@wz + bz ; cpart = f_src@w + b
__global__ void __launch_bounds__(256) k_gemmA(
    const float* __restrict__ fsrc,
    const float* __restrict__ wz, const float* __restrict__ w,
    const float* __restrict__ bz, const float* __restrict__ b, int n)
{
    extern __shared__ char smemraw[];
    u64*   sW1 = (u64*)smemraw;            // wz, 8192 u64
    u64*   sW2 = sW1 + 8192;               // w
    float* sX  = (float*)(sW2 + 8192);     // 128 x XPITCH floats (uses both x slots)
    int tid = threadIdx.x;
    {
        const ulonglong2* a = (const ulonglong2*)wz;
        const ulonglong2* c = (const ulonglong2*)w;
        ulonglong2* da = (ulonglong2*)sW1;
        ulonglong2* dc = (ulonglong2*)sW2;
        for (int i = tid; i < 4096; i += 256) { da[i] = a[i]; dc[i] = c[i]; }
    }
    int rowBase = blockIdx.x * 128;
    {
        const float4* s4 = (const float4*)fsrc;
        for (int j = tid; j < 4096; j += 256) {
            int r = j >> 5, c4 = j & 31;
            float4 v = (rowBase + r < n) ? s4[(rowBase + r) * 32 + c4] : make_float4(0.f,0.f,0.f,0.f);
            *(float4*)(&sX[r * XPITCH + c4 * 4]) = v;
        }
    }
    __syncthreads();
    int wid = tid >> 5, lane = tid & 31;
    int cs = wid & 3, rg = wid >> 2;
    int tx = lane & 3, ry = lane >> 2;
    int cp0 = cs * 16 + tx * 4;
    int colBase = cp0 * 2;
    for (int pass = 0; pass < 8; pass++) {
        int r = pass * 16 + rg * 8 + ry;
        int grow = rowBase + r;
        u64 a0=0,a1=0,a2=0,a3=0, c0=0,c1=0,c2=0,c3=0;
        const float* xrow = &sX[r * XPITCH];
        #pragma unroll 8
        for (int k = 0; k < 128; k++) {
            u64 xv = dup2(xrow[k]);
            const u64* w1 = &sW1[k * 64 + cp0];
            const u64* w2 = &sW2[k * 64 + cp0];
            ulonglong2 wa = *(const ulonglong2*)(w1);
            ulonglong2 wb = *(const ulonglong2*)(w1 + 2);
            ulonglong2 wc = *(const ulonglong2*)(w2);
            ulonglong2 wd = *(const ulonglong2*)(w2 + 2);
            fma2(a0, xv, wa.x); fma2(a1, xv, wa.y); fma2(a2, xv, wb.x); fma2(a3, xv, wb.y);
            fma2(c0, xv, wc.x); fma2(c1, xv, wc.y); fma2(c2, xv, wd.x); fma2(c3, xv, wd.y);
        }
        if (grow < n) {
            float2 f0=unpack2(a0), f1=unpack2(a1), f2=unpack2(a2), f3=unpack2(a3);
            float2 e0=unpack2(c0), e1=unpack2(c1), e2=unpack2(c2), e3=unpack2(c3);
            float* oz = &g_zp[grow * 128 + colBase];
            float* oc = &g_cp[grow * 128 + colBase];
            float4 v;
            v.x=f0.x+bz[colBase+0]; v.y=f0.y+bz[colBase+1]; v.z=f1.x+bz[colBase+2]; v.w=f1.y+bz[colBase+3];
            *(float4*)(oz) = v;
            v.x=f2.x+bz[colBase+4]; v.y=f2.y+bz[colBase+5]; v.z=f3.x+bz[colBase+6]; v.w=f3.y+bz[colBase+7];
            *(float4*)(oz + 4) = v;
            v.x=e0.x+b[colBase+0]; v.y=e0.y+b[colBase+1]; v.z=e1.x+b[colBase+2]; v.w=e1.y+b[colBase+3];
            *(float4*)(oc) = v;
            v.x=e2.x+b[colBase+4]; v.y=e2.y+b[colBase+5]; v.z=e3.x+b[colBase+6]; v.w=e3.y+b[colBase+7];
            *(float4*)(oc + 4) = v;
        }
    }
}

// p = sigmoid(f_dst@wr + h@ur + br) * h
__global__ void __launch_bounds__(256) k_gemmB(
    const float* __restrict__ fdst, const float* __restrict__ h,
    const float* __restrict__ wr, const float* __restrict__ ur,
    const float* __restrict__ br, int n)
{
    extern __shared__ char smemraw[];
    u64*   sW1 = (u64*)smemraw;            // wr
    u64*   sW2 = sW1 + 8192;               // ur
    float* sXa = (float*)(sW2 + 8192);     // f_dst rows, 64 x XPITCH
    float* sXb = sXa + 64 * XPITCH;        // h rows
    int tid = threadIdx.x;
    {
        const ulonglong2* a = (const ulonglong2*)wr;
        const ulonglong2* c = (const ulonglong2*)ur;
        ulonglong2* da = (ulonglong2*)sW1;
        ulonglong2* dc = (ulonglong2*)sW2;
        for (int i = tid; i < 4096; i += 256) { da[i] = a[i]; dc[i] = c[i]; }
    }
    int wid = tid >> 5, lane = tid & 31;
    int cs = wid & 3, rg = wid >> 2;
    int tx = lane & 3, ry = lane >> 2;
    int cp0 = cs * 16 + tx * 4;
    int colBase = cp0 * 2;
    for (int chunk = 0; chunk < 2; chunk++) {
        int rowBase = blockIdx.x * 128 + chunk * 64;
        __syncthreads();
        {
            const float4* sa4 = (const float4*)fdst;
            const float4* sb4 = (const float4*)h;
            for (int j = tid; j < 2048; j += 256) {
                int r = j >> 5, c4 = j & 31;
                bool ok = (rowBase + r < n);
                float4 va = ok ? sa4[(rowBase + r) * 32 + c4] : make_float4(0.f,0.f,0.f,0.f);
                float4 vb = ok ? sb4[(rowBase + r) * 32 + c4] : make_float4(0.f,0.f,0.f,0.f);
                *(float4*)(&sXa[r * XPITCH + c4 * 4]) = va;
                *(float4*)(&sXb[r * XPITCH + c4 * 4]) = vb;
            }
        }
        __syncthreads();
        for (int pass = 0; pass < 4; pass++) {
            int r = pass * 16 + rg * 8 + ry;
            int grow = rowBase + r;
            u64 a0=0,a1=0,a2=0,a3=0;
            const float* xa = &sXa[r * XPITCH];
            const float* xb = &sXb[r * XPITCH];
            #pragma unroll 8
            for (int k = 0; k < 128; k++) {
                u64 xv1 = dup2(xa[k]);
                u64 xv2 = dup2(xb[k]);
                const u64* w1 = &sW1[k * 64 + cp0];
                const u64* w2 = &sW2[k * 64 + cp0];
                ulonglong2 wa = *(const ulonglong2*)(w1);
                ulonglong2 wb = *(const ulonglong2*)(w1 + 2);
                ulonglong2 wc = *(const ulonglong2*)(w2);
                ulonglong2 wd = *(const ulonglong2*)(w2 + 2);
                fma2(a0, xv1, wa.x); fma2(a1, xv1, wa.y); fma2(a2, xv1, wb.x); fma2(a3, xv1, wb.y);
                fma2(a0, xv2, wc.x); fma2(a1, xv2, wc.y); fma2(a2, xv2, wd.x); fma2(a3, xv2, wd.y);
            }
            if (grow < n) {
                float2 f0=unpack2(a0), f1=unpack2(a1), f2=unpack2(a2), f3=unpack2(a3);
                const float* hr = &sXb[r * XPITCH + colBase];
                float acc[8] = {f0.x,f0.y,f1.x,f1.y,f2.x,f2.y,f3.x,f3.y};
                float4 v;
                float* op = &g_p[grow * 128 + colBase];
                v.x = sigmoidf(acc[0]+br[colBase+0]) * hr[0];
                v.y = sigmoidf(acc[1]+br[colBase+1]) * hr[1];
                v.z = sigmoidf(acc[2]+br[colBase+2]) * hr[2];
                v.w = sigmoidf(acc[3]+br[colBase+3]) * hr[3];
                *(float4*)(op) = v;
                v.x = sigmoidf(acc[4]+br[colBase+4]) * hr[4];
                v.y = sigmoidf(acc[5]+br[colBase+5]) * hr[5];
                v.z = sigmoidf(acc[6]+br[colBase+6]) * hr[6];
                v.w = sigmoidf(acc[7]+br[colBase+7]) * hr[7];
                *(float4*)(op + 4) = v;
            }
        }
    }
}

// z = sigmoid(zp + s@uz); ht = tanh(cp + q@u); out = (1-z)*s + z*ht
__global__ void __launch_bounds__(256) k_gemmC(
    const float* __restrict__ uz, const float* __restrict__ u,
    float* __restrict__ out, int n)
{
    extern __shared__ char smemraw[];
    u64*   sW1 = (u64*)smemraw;            // uz
    u64*   sW2 = sW1 + 8192;               // u
    float* sXs = (float*)(sW2 + 8192);     // s rows
    float* sXq = sXs + 64 * XPITCH;        // q rows
    int tid = threadIdx.x;
    {
        const ulonglong2* a = (const ulonglong2*)uz;
        const ulonglong2* c = (const ulonglong2*)u;
        ulonglong2* da = (ulonglong2*)sW1;
        ulonglong2* dc = (ulonglong2*)sW2;
        for (int i = tid; i < 4096; i += 256) { da[i] = a[i]; dc[i] = c[i]; }
    }
    int wid = tid >> 5, lane = tid & 31;
    int cs = wid & 3, rg = wid >> 2;
    int tx = lane & 3, ry = lane >> 2;
    int cp0 = cs * 16 + tx * 4;
    int colBase = cp0 * 2;
    for (int chunk = 0; chunk < 2; chunk++) {
        int rowBase = blockIdx.x * 128 + chunk * 64;
        __syncthreads();
        {
            const float4* sa4 = (const float4*)g_s;
            const float4* sb4 = (const float4*)g_q;
            for (int j = tid; j < 2048; j += 256) {
                int r = j >> 5, c4 = j & 31;
                bool ok = (rowBase + r < n);
                float4 va = ok ? sa4[(rowBase + r) * 32 + c4] : make_float4(0.f,0.f,0.f,0.f);
                float4 vb = ok ? sb4[(rowBase + r) * 32 + c4] : make_float4(0.f,0.f,0.f,0.f);
                *(float4*)(&sXs[r * XPITCH + c4 * 4]) = va;
                *(float4*)(&sXq[r * XPITCH + c4 * 4]) = vb;
            }
        }
        __syncthreads();
        for (int pass = 0; pass < 4; pass++) {
            int r = pass * 16 + rg * 8 + ry;
            int grow = rowBase + r;
            u64 za0=0,za1=0,za2=0,za3=0, ca0=0,ca1=0,ca2=0,ca3=0;
            const float* xs = &sXs[r * XPITCH];
            const float* xq = &sXq[r * XPITCH];
            #pragma unroll 8
            for (int k = 0; k < 128; k++) {
                u64 xv1 = dup2(xs[k]);
                u64 xv2 = dup2(xq[k]);
                const u64* w1 = &sW1[k * 64 + cp0];
                const u64* w2 = &sW2[k * 64 + cp0];
                ulonglong2 wa = *(const ulonglong2*)(w1);
                ulonglong2 wb = *(const ulonglong2*)(w1 + 2);
                ulonglong2 wc = *(const ulonglong2*)(w2);
                ulonglong2 wd = *(const ulonglong2*)(w2 + 2);
                fma2(za0, xv1, wa.x); fma2(za1, xv1, wa.y); fma2(za2, xv1, wb.x); fma2(za3, xv1, wb.y);
                fma2(ca0, xv2, wc.x); fma2(ca1, xv2, wc.y); fma2(ca2, xv2, wd.x); fma2(ca3, xv2, wd.y);
            }
            if (grow < n) {
                float2 z0=unpack2(za0), z1=unpack2(za1), z2=unpack2(za2), z3=unpack2(za3);
                float2 t0=unpack2(ca0), t1=unpack2(ca1), t2=unpack2(ca2), t3=unpack2(ca3);
                float zacc[8] = {z0.x,z0.y,z1.x,z1.y,z2.x,z2.y,z3.x,z3.y};
                float tacc[8] = {t0.x,t0.y,t1.x,t1.y,t2.x,t2.y,t3.x,t3.y};
                const float* zp = &g_zp[grow * 128 + colBase];
                const float* cp = &g_cp[grow * 128 + colBase];
                const float* sv = &sXs[r * XPITCH + colBase];
                float o[8];
                #pragma unroll
                for (int j = 0; j < 8; j++) {
                    float zj = sigmoidf(zp[j] + zacc[j]);
                    float tj = tanhf(cp[j] + tacc[j]);
                    o[j] = (1.0f - zj) * sv[j] + zj * tj;
                }
                float* od = &out[grow * 128 + colBase];
                *(float4*)(od)     = make_float4(o[0], o[1], o[2], o[3]);
                *(float4*)(od + 4) = make_float4(o[4], o[5], o[6], o[7]);
            }
        }
    }
}

// ---------------- launch ----------------
extern "C" void kernel_launch(void* const* d_in, const int* in_sizes, int n_in,
                              void* d_out, int out_size)
{
    const float* h    = (const float*)d_in[0];
    const float* fsrc = (const float*)d_in[1];
    const float* fdst = (const float*)d_in[2];
    const int*   src  = (const int*)d_in[3];
    const int*   dst  = (const int*)d_in[4];
    const float* wz   = (const float*)d_in[5];
    const float* uz   = (const float*)d_in[6];
    const float* bz   = (const float*)d_in[7];
    const float* wr   = (const float*)d_in[8];
    const float* ur   = (const float*)d_in[9];
    const float* br   = (const float*)d_in[10];
    const float* w    = (const float*)d_in[11];
    const float* u    = (const float*)d_in[12];
    const float* b    = (const float*)d_in[13];
    float* out = (float*)d_out;

    int n = in_sizes[0] / D;
    int e = in_sizes[3];
    if (n > NMAX || e > EMAX) return;

    cudaFuncSetAttribute(k_gemmA, cudaFuncAttributeMaxDynamicSharedMemorySize, GEMM_SMEM);
    cudaFuncSetAttribute(k_gemmB, cudaFuncAttributeMaxDynamicSharedMemorySize, GEMM_SMEM);
    cudaFuncSetAttribute(k_gemmC, cudaFuncAttributeMaxDynamicSharedMemorySize, GEMM_SMEM);

    int gemmBlocks = (n + 127) / 128;

    k_zero<<<(n + 255) / 256, 256>>>(n);
    k_hist<<<(e + 255) / 256, 256>>>(dst, e);
    k_scan<<<1, 1024>>>(n, e);
    k_scatter<<<(e + 255) / 256, 256>>>(src, dst, e);
    k_gemmB<<<gemmBlocks, 256, GEMM_SMEM>>>(fdst, h, wr, ur, br, n);
    k_gemmA<<<gemmBlocks, 256, GEMM_SMEM>>>(fsrc, wz, w, bz, b, n);
    k_reduce<<<(n + 7) / 8, 256>>>(h, n);
    k_gemmC<<<gemmBlocks, 256, GEMM_SMEM>>>(uz, u, out, n);
}

// round 2
// speedup vs baseline: 1.6173x; 1.6173x over previous
#include <cuda_runtime.h>

#define NMAX 100000
#define EMAX 1600000
#define D    128

// ---------------- scratch (static device allocations) ----------------
__device__ float g_p [NMAX * D];   // p[v] = sigmoid(f_dst@wr + h@ur + br) * h
__device__ float g_zp[NMAX * D];   // f_src@wz + bz
__device__ float g_cp[NMAX * D];   // f_src@w  + b
__device__ float g_s [NMAX * D];   // segment_sum(h[src], dst)
__device__ float g_q [NMAX * D];   // segment_sum(p[src], dst)
__device__ int   g_cnt[NMAX];
__device__ int   g_off[NMAX + 1];
__device__ int   g_cur[NMAX];
__device__ int   g_perm[EMAX];

typedef unsigned long long u64;

// ---------------- f32x2 packed-FMA helpers (FFMA2 in SASS) ----------------
__device__ __forceinline__ u64 dup2(float x) {
    u64 r; asm("mov.b64 %0,{%1,%1};" : "=l"(r) : "f"(x)); return r;
}
__device__ __forceinline__ void fma2(u64 &acc, u64 a, u64 b) {
    asm("fma.rn.f32x2 %0,%1,%2,%0;" : "+l"(acc) : "l"(a), "l"(b));
}
__device__ __forceinline__ float2 unpack2(u64 v) {
    float2 r; asm("mov.b64 {%0,%1},%2;" : "=f"(r.x), "=f"(r.y) : "l"(v)); return r;
}
__device__ __forceinline__ float sigmoidf(float x) { return 1.0f / (1.0f + __expf(-x)); }

// ---------------- CSR build ----------------
__global__ void k_zero(int n) {
    int i = blockIdx.x * blockDim.x + threadIdx.x;
    if (i < n) g_cnt[i] = 0;
}

__global__ void k_hist(const int* __restrict__ dst, int e) {
    int i = blockIdx.x * blockDim.x + threadIdx.x;
    if (i < e) atomicAdd(&g_cnt[dst[i]], 1);
}

__global__ void k_scan(int n, int e) {
    __shared__ int sm[1024];
    int t = threadIdx.x;
    int CH = (n + 1023) >> 10;
    int base = t * CH;
    int sum = 0;
    for (int i = 0; i < CH; i++) {
        int idx = base + i;
        if (idx < n) sum += g_cnt[idx];
    }
    sm[t] = sum;
    __syncthreads();
    for (int off = 1; off < 1024; off <<= 1) {
        int v = (t >= off) ? sm[t - off] : 0;
        __syncthreads();
        sm[t] += v;
        __syncthreads();
    }
    int run = sm[t] - sum;  // exclusive prefix for this chunk
    for (int i = 0; i < CH; i++) {
        int idx = base + i;
        if (idx < n) {
            g_off[idx] = run;
            g_cur[idx] = run;
            run += g_cnt[idx];
        }
    }
    if (t == 0) g_off[n] = e;
}

__global__ void k_scatter(const int* __restrict__ src, const int* __restrict__ dst, int e) {
    int i = blockIdx.x * blockDim.x + threadIdx.x;
    if (i < e) {
        int d = dst[i];
        int pos = atomicAdd(&g_cur[d], 1);
        g_perm[pos] = src[i];
    }
}

// ---------------- segment reduce: warp per node ----------------
__global__ void k_reduce(const float* __restrict__ h, int n) {
    int gw = (blockIdx.x * blockDim.x + threadIdx.x) >> 5;
    int lane = threadIdx.x & 31;
    if (gw >= n) return;
    int i0 = g_off[gw], i1 = g_off[gw + 1];
    const float4* h4 = (const float4*)h;
    const float4* p4 = (const float4*)g_p;
    float4 sa = make_float4(0.f, 0.f, 0.f, 0.f);
    float4 qa = make_float4(0.f, 0.f, 0.f, 0.f);
    int i = i0;
    for (; i + 1 < i1; i += 2) {
        int u0 = g_perm[i], u1 = g_perm[i + 1];
        float4 a0 = h4[u0 * 32 + lane];
        float4 b0 = p4[u0 * 32 + lane];
        float4 a1 = h4[u1 * 32 + lane];
        float4 b1 = p4[u1 * 32 + lane];
        sa.x += a0.x + a1.x; sa.y += a0.y + a1.y; sa.z += a0.z + a1.z; sa.w += a0.w + a1.w;
        qa.x += b0.x + b1.x; qa.y += b0.y + b1.y; qa.z += b0.z + b1.z; qa.w += b0.w + b1.w;
    }
    if (i < i1) {
        int u0 = g_perm[i];
        float4 a0 = h4[u0 * 32 + lane];
        float4 b0 = p4[u0 * 32 + lane];
        sa.x += a0.x; sa.y += a0.y; sa.z += a0.z; sa.w += a0.w;
        qa.x += b0.x; qa.y += b0.y; qa.z += b0.z; qa.w += b0.w;
    }
    ((float4*)g_s)[gw * 32 + lane] = sa;
    ((float4*)g_q)[gw * 32 + lane] = qa;
}

// ---------------- GEMM common layout ----------------
// block = 256 threads; thread grid 16(ty) x 16(tx).
// Block tile: 64 rows x 128 cols. Thread tile: 4 rows x 8 cols (4 u64 accumulators
// per matrix). Weights in smem with bank skew: u64 col j stored at j + 2*(j>>4),
// row pitch 72 u64 -> each LDS.128 across 16 lanes covers every 16B bank-granule
// exactly twice (2 wavefronts, minimum possible).
#define WPITCH 72
#define WBYTES (128 * WPITCH * 8)       // 73728 per matrix
#define XPITCH 132
#define XBYTES (64 * XPITCH * 4)        // 33792 per x tile
#define SMEM_A (2 * WBYTES + XBYTES)            // 181248
#define SMEM_BC (2 * WBYTES + 2 * XBYTES)       // 215040

__device__ __forceinline__ void load_weights_skewed(const float* __restrict__ w1,
                                                    const float* __restrict__ w2,
                                                    u64* sW1, u64* sW2, int tid) {
    const u64* a = (const u64*)w1;
    const u64* c = (const u64*)w2;
    for (int i = tid; i < 8192; i += 256) {
        int k = i >> 6, j = i & 63;
        int phys = k * WPITCH + j + 2 * (j >> 4);
        sW1[phys] = a[i];
        sW2[phys] = c[i];
    }
}

__device__ __forceinline__ void load_xtile(const float* __restrict__ x, float* sX,
                                           int rowBase, int n, int tid) {
    const float4* s4 = (const float4*)x;
    for (int i = tid; i < 64 * 32; i += 256) {
        int r = i >> 5, c4 = i & 31;
        float4 v = (rowBase + r < n) ? s4[(size_t)(rowBase + r) * 32 + c4]
                                     : make_float4(0.f, 0.f, 0.f, 0.f);
        *(float4*)(&sX[r * XPITCH + c4 * 4]) = v;
    }
}

// zp = f_src@wz + bz ; cp = f_src@w + b   (one x, two outputs)
__global__ void __launch_bounds__(256) k_gemmA(
    const float* __restrict__ fsrc,
    const float* __restrict__ wz, const float* __restrict__ w,
    const float* __restrict__ bz, const float* __restrict__ b, int n)
{
    extern __shared__ char smemraw[];
    u64*   sW1 = (u64*)smemraw;
    u64*   sW2 = sW1 + 128 * WPITCH;
    float* sX  = (float*)(sW2 + 128 * WPITCH);
    int tid = threadIdx.x;
    int rowBase = blockIdx.x * 64;

    load_weights_skewed(wz, w, sW1, sW2, tid);
    load_xtile(fsrc, sX, rowBase, n, tid);
    __syncthreads();

    int tx = tid & 15, ty = tid >> 4;
    int r0 = ty * 4;
    int col = tx * 8;
    int twb = tx * 4 + 2 * (tx >> 2);

    u64 a[4][4], c[4][4];
    #pragma unroll
    for (int i = 0; i < 4; i++)
        #pragma unroll
        for (int j = 0; j < 4; j++) { a[i][j] = 0; c[i][j] = 0; }

    for (int k4 = 0; k4 < 32; k4++) {
        float xv[4][4];
        #pragma unroll
        for (int i = 0; i < 4; i++)
            *(float4*)xv[i] = *(const float4*)(&sX[(r0 + i) * XPITCH + k4 * 4]);
        #pragma unroll
        for (int kk = 0; kk < 4; kk++) {
            int k = k4 * 4 + kk;
            const u64* w1 = &sW1[k * WPITCH + twb];
            const u64* w2 = &sW2[k * WPITCH + twb];
            ulonglong2 wa = *(const ulonglong2*)(w1);
            ulonglong2 wb = *(const ulonglong2*)(w1 + 2);
            ulonglong2 wc = *(const ulonglong2*)(w2);
            ulonglong2 wd = *(const ulonglong2*)(w2 + 2);
            #pragma unroll
            for (int i = 0; i < 4; i++) {
                u64 xd = dup2(xv[i][kk]);
                fma2(a[i][0], xd, wa.x); fma2(a[i][1], xd, wa.y);
                fma2(a[i][2], xd, wb.x); fma2(a[i][3], xd, wb.y);
                fma2(c[i][0], xd, wc.x); fma2(c[i][1], xd, wc.y);
                fma2(c[i][2], xd, wd.x); fma2(c[i][3], xd, wd.y);
            }
        }
    }

    float bza[8], ba[8];
    *(float4*)(bza)     = *(const float4*)(&bz[col]);
    *(float4*)(bza + 4) = *(const float4*)(&bz[col + 4]);
    *(float4*)(ba)      = *(const float4*)(&b[col]);
    *(float4*)(ba + 4)  = *(const float4*)(&b[col + 4]);

    #pragma unroll
    for (int i = 0; i < 4; i++) {
        int grow = rowBase + r0 + i;
        if (grow >= n) continue;
        float az[8], ac[8];
        #pragma unroll
        for (int j = 0; j < 4; j++) {
            float2 va = unpack2(a[i][j]); az[2*j] = va.x + bza[2*j]; az[2*j+1] = va.y + bza[2*j+1];
            float2 vc = unpack2(c[i][j]); ac[2*j] = vc.x + ba[2*j];  ac[2*j+1] = vc.y + ba[2*j+1];
        }
        float* oz = &g_zp[(size_t)grow * 128 + col];
        float* oc = &g_cp[(size_t)grow * 128 + col];
        *(float4*)(oz)     = *(float4*)(az);
        *(float4*)(oz + 4) = *(float4*)(az + 4);
        *(float4*)(oc)     = *(float4*)(ac);
        *(float4*)(oc + 4) = *(float4*)(ac + 4);
    }
}

// p = sigmoid(f_dst@wr + h@ur + br) * h    (two x, one output)
__global__ void __launch_bounds__(256) k_gemmB(
    const float* __restrict__ fdst, const float* __restrict__ h,
    const float* __restrict__ wr, const float* __restrict__ ur,
    const float* __restrict__ br, int n)
{
    extern __shared__ char smemraw[];
    u64*   sW1 = (u64*)smemraw;
    u64*   sW2 = sW1 + 128 * WPITCH;
    float* sXa = (float*)(sW2 + 128 * WPITCH);
    float* sXb = sXa + 64 * XPITCH;
    int tid = threadIdx.x;
    int rowBase = blockIdx.x * 64;

    load_weights_skewed(wr, ur, sW1, sW2, tid);
    load_xtile(fdst, sXa, rowBase, n, tid);
    load_xtile(h,    sXb, rowBase, n, tid);
    __syncthreads();

    int tx = tid & 15, ty = tid >> 4;
    int r0 = ty * 4;
    int col = tx * 8;
    int twb = tx * 4 + 2 * (tx >> 2);

    u64 a[4][4];
    #pragma unroll
    for (int i = 0; i < 4; i++)
        #pragma unroll
        for (int j = 0; j < 4; j++) a[i][j] = 0;

    for (int k4 = 0; k4 < 32; k4++) {
        float xa[4][4], xb[4][4];
        #pragma unroll
        for (int i = 0; i < 4; i++) {
            *(float4*)xa[i] = *(const float4*)(&sXa[(r0 + i) * XPITCH + k4 * 4]);
            *(float4*)xb[i] = *(const float4*)(&sXb[(r0 + i) * XPITCH + k4 * 4]);
        }
        #pragma unroll
        for (int kk = 0; kk < 4; kk++) {
            int k = k4 * 4 + kk;
            const u64* w1 = &sW1[k * WPITCH + twb];
            const u64* w2 = &sW2[k * WPITCH + twb];
            ulonglong2 wa = *(const ulonglong2*)(w1);
            ulonglong2 wb = *(const ulonglong2*)(w1 + 2);
            ulonglong2 wc = *(const ulonglong2*)(w2);
            ulonglong2 wd = *(const ulonglong2*)(w2 + 2);
            #pragma unroll
            for (int i = 0; i < 4; i++) {
                u64 x1 = dup2(xa[i][kk]);
                u64 x2 = dup2(xb[i][kk]);
                fma2(a[i][0], x1, wa.x); fma2(a[i][1], x1, wa.y);
                fma2(a[i][2], x1, wb.x); fma2(a[i][3], x1, wb.y);
                fma2(a[i][0], x2, wc.x); fma2(a[i][1], x2, wc.y);
                fma2(a[i][2], x2, wd.x); fma2(a[i][3], x2, wd.y);
            }
        }
    }

    float brv[8];
    *(float4*)(brv)     = *(const float4*)(&br[col]);
    *(float4*)(brv + 4) = *(const float4*)(&br[col + 4]);

    #pragma unroll
    for (int i = 0; i < 4; i++) {
        int grow = rowBase + r0 + i;
        if (grow >= n) continue;
        const float* hr = &sXb[(r0 + i) * XPITCH + col];
        float o[8];
        #pragma unroll
        for (int j = 0; j < 4; j++) {
            float2 v = unpack2(a[i][j]);
            o[2*j]   = sigmoidf(v.x + brv[2*j])   * hr[2*j];
            o[2*j+1] = sigmoidf(v.y + brv[2*j+1]) * hr[2*j+1];
        }
        float* op = &g_p[(size_t)grow * 128 + col];
        *(float4*)(op)     = *(float4*)(o);
        *(float4*)(op + 4) = *(float4*)(o + 4);
    }
}

// z = sigmoid(zp + s@uz); ht = tanh(cp + q@u); out = (1-z)*s + z*ht
__global__ void __launch_bounds__(256) k_gemmC(
    const float* __restrict__ uz, const float* __restrict__ u,
    float* __restrict__ out, int n)
{
    extern __shared__ char smemraw[];
    u64*   sW1 = (u64*)smemraw;
    u64*   sW2 = sW1 + 128 * WPITCH;
    float* sXs = (float*)(sW2 + 128 * WPITCH);
    float* sXq = sXs + 64 * XPITCH;
    int tid = threadIdx.x;
    int rowBase = blockIdx.x * 64;

    load_weights_skewed(uz, u, sW1, sW2, tid);
    load_xtile(g_s, sXs, rowBase, n, tid);
    load_xtile(g_q, sXq, rowBase, n, tid);
    __syncthreads();

    int tx = tid & 15, ty = tid >> 4;
    int r0 = ty * 4;
    int col = tx * 8;
    int twb = tx * 4 + 2 * (tx >> 2);

    u64 za[4][4], ca[4][4];
    #pragma unroll
    for (int i = 0; i < 4; i++)
        #pragma unroll
        for (int j = 0; j < 4; j++) { za[i][j] = 0; ca[i][j] = 0; }

    for (int k4 = 0; k4 < 32; k4++) {
        float xs[4][4], xq[4][4];
        #pragma unroll
        for (int i = 0; i < 4; i++) {
            *(float4*)xs[i] = *(const float4*)(&sXs[(r0 + i) * XPITCH + k4 * 4]);
            *(float4*)xq[i] = *(const float4*)(&sXq[(r0 + i) * XPITCH + k4 * 4]);
        }
        #pragma unroll
        for (int kk = 0; kk < 4; kk++) {
            int k = k4 * 4 + kk;
            const u64* w1 = &sW1[k * WPITCH + twb];
            const u64* w2 = &sW2[k * WPITCH + twb];
            ulonglong2 wa = *(const ulonglong2*)(w1);
            ulonglong2 wb = *(const ulonglong2*)(w1 + 2);
            ulonglong2 wc = *(const ulonglong2*)(w2);
            ulonglong2 wd = *(const ulonglong2*)(w2 + 2);
            #pragma unroll
            for (int i = 0; i < 4; i++) {
                u64 x1 = dup2(xs[i][kk]);
                u64 x2 = dup2(xq[i][kk]);
                fma2(za[i][0], x1, wa.x); fma2(za[i][1], x1, wa.y);
                fma2(za[i][2], x1, wb.x); fma2(za[i][3], x1, wb.y);
                fma2(ca[i][0], x2, wc.x); fma2(ca[i][1], x2, wc.y);
                fma2(ca[i][2], x2, wd.x); fma2(ca[i][3], x2, wd.y);
            }
        }
    }

    #pragma unroll
    for (int i = 0; i < 4; i++) {
        int grow = rowBase + r0 + i;
        if (grow >= n) continue;
        const float* zp = &g_zp[(size_t)grow * 128 + col];
        const float* cp = &g_cp[(size_t)grow * 128 + col];
        const float* sv = &sXs[(r0 + i) * XPITCH + col];
        float o[8];
        #pragma unroll
        for (int j = 0; j < 4; j++) {
            float2 vz = unpack2(za[i][j]);
            float2 vc = unpack2(ca[i][j]);
            float z0 = sigmoidf(zp[2*j]   + vz.x);
            float z1 = sigmoidf(zp[2*j+1] + vz.y);
            float t0 = tanhf(cp[2*j]   + vc.x);
            float t1 = tanhf(cp[2*j+1] + vc.y);
            o[2*j]   = (1.0f - z0) * sv[2*j]   + z0 * t0;
            o[2*j+1] = (1.0f - z1) * sv[2*j+1] + z1 * t1;
        }
        float* od = &out[(size_t)grow * 128 + col];
        *(float4*)(od)     = *(float4*)(o);
        *(float4*)(od + 4) = *(float4*)(o + 4);
    }
}

// ---------------- launch ----------------
extern "C" void kernel_launch(void* const* d_in, const int* in_sizes, int n_in,
                              void* d_out, int out_size)
{
    const float* h    = (const float*)d_in[0];
    const float* fsrc = (const float*)d_in[1];
    const float* fdst = (const float*)d_in[2];
    const int*   src  = (const int*)d_in[3];
    const int*   dst  = (const int*)d_in[4];
    const float* wz   = (const float*)d_in[5];
    const float* uz   = (const float*)d_in[6];
    const float* bz   = (const float*)d_in[7];
    const float* wr   = (const float*)d_in[8];
    const float* ur   = (const float*)d_in[9];
    const float* br   = (const float*)d_in[10];
    const float* w    = (const float*)d_in[11];
    const float* u    = (const float*)d_in[12];
    const float* b    = (const float*)d_in[13];
    float* out = (float*)d_out;

    int n = in_sizes[0] / D;
    int e = in_sizes[3];
    if (n > NMAX || e > EMAX) return;

    cudaFuncSetAttribute(k_gemmA, cudaFuncAttributeMaxDynamicSharedMemorySize, SMEM_A);
    cudaFuncSetAttribute(k_gemmB, cudaFuncAttributeMaxDynamicSharedMemorySize, SMEM_BC);
    cudaFuncSetAttribute(k_gemmC, cudaFuncAttributeMaxDynamicSharedMemorySize, SMEM_BC);

    int gemmBlocks = (n + 63) / 64;

    k_zero<<<(n + 255) / 256, 256>>>(n);
    k_hist<<<(e + 255) / 256, 256>>>(dst, e);
    k_scan<<<1, 1024>>>(n, e);
    k_scatter<<<(e + 255) / 256, 256>>>(src, dst, e);
    k_gemmB<<<gemmBlocks, 256, SMEM_BC>>>(fdst, h, wr, ur, br, n);
    k_gemmA<<<gemmBlocks, 256, SMEM_A>>>(fsrc, wz, w, bz, b, n);
    k_reduce<<<(n + 7) / 8, 256>>>(h, n);
    k_gemmC<<<gemmBlocks, 256, SMEM_BC>>>(uz, u, out, n);
}

// round 5
// speedup vs baseline: 2.2568x; 1.3954x over previous
#include <cuda_runtime.h>
#include <cstdint>

#define NMAX 100000
#define EMAX 1600000

// ---------------- scratch ----------------
__device__ float g_p [NMAX * 128];
__device__ float g_zp[NMAX * 128];
__device__ float g_cp[NMAX * 128];
__device__ float g_s [NMAX * 128];
__device__ float g_q [NMAX * 128];
__device__ int   g_cnt[NMAX];
__device__ int   g_off[NMAX + 1];
__device__ int   g_cur[NMAX];
__device__ int   g_perm[EMAX];
__device__ uint4 g_wimg[6 * 4096];   // 6 weight images, 64KB each, B-fragment order

__device__ __forceinline__ float sigmoidf(float x) { return 1.0f / (1.0f + __expf(-x)); }
__device__ __forceinline__ float tanh_fast(float x) {
    return __fdividef(2.0f, 1.0f + __expf(-2.0f * x)) - 1.0f;
}
__device__ __forceinline__ uint32_t totf32(float f) {
    uint32_t r; asm("cvt.rna.tf32.f32 %0,%1;" : "=r"(r) : "f"(f)); return r;
}

// ---------------- mma.sync m16n8k8 tf32 ----------------
__device__ __forceinline__ void mma8(float* d, const uint32_t* a, uint32_t b0, uint32_t b1) {
    asm("mma.sync.aligned.m16n8k8.row.col.f32.tf32.tf32.f32 "
        "{%0,%1,%2,%3},{%4,%5,%6,%7},{%8,%9},{%0,%1,%2,%3};"
        : "+f"(d[0]), "+f"(d[1]), "+f"(d[2]), "+f"(d[3])
        : "r"(a[0]), "r"(a[1]), "r"(a[2]), "r"(a[3]), "r"(b0), "r"(b1));
}

// ---------------- CSR build ----------------
__global__ void k_zero(int n) {
    int i = blockIdx.x * blockDim.x + threadIdx.x;
    if (i < n) g_cnt[i] = 0;
}
__global__ void k_hist(const int* __restrict__ dst, int e) {
    int i = blockIdx.x * blockDim.x + threadIdx.x;
    if (i < e) atomicAdd(&g_cnt[dst[i]], 1);
}
__global__ void k_scan(int n, int e) {
    __shared__ int sm[1024];
    int t = threadIdx.x;
    int CH = (n + 1023) >> 10;
    int base = t * CH;
    int sum = 0;
    for (int i = 0; i < CH; i++) { int idx = base + i; if (idx < n) sum += g_cnt[idx]; }
    sm[t] = sum;
    __syncthreads();
    for (int off = 1; off < 1024; off <<= 1) {
        int v = (t >= off) ? sm[t - off] : 0;
        __syncthreads();
        sm[t] += v;
        __syncthreads();
    }
    int run = sm[t] - sum;
    for (int i = 0; i < CH; i++) {
        int idx = base + i;
        if (idx < n) { g_off[idx] = run; g_cur[idx] = run; run += g_cnt[idx]; }
    }
    if (t == 0) g_off[n] = e;
}
__global__ void k_scatter(const int* __restrict__ src, const int* __restrict__ dst, int e) {
    int i = blockIdx.x * blockDim.x + threadIdx.x;
    if (i < e) {
        int d = dst[i];
        int pos = atomicAdd(&g_cur[d], 1);
        g_perm[pos] = src[i];
    }
}

// ---------------- segment reduce: warp per node ----------------
__global__ void k_reduce(const float* __restrict__ h, int n) {
    int gw = (blockIdx.x * blockDim.x + threadIdx.x) >> 5;
    int lane = threadIdx.x & 31;
    if (gw >= n) return;
    int i0 = g_off[gw], i1 = g_off[gw + 1];
    const float4* h4 = (const float4*)h;
    const float4* p4 = (const float4*)g_p;
    float4 sa = make_float4(0.f, 0.f, 0.f, 0.f);
    float4 qa = make_float4(0.f, 0.f, 0.f, 0.f);
    int i = i0;
    for (; i + 1 < i1; i += 2) {
        int u0 = g_perm[i], u1 = g_perm[i + 1];
        float4 a0 = h4[u0 * 32 + lane];
        float4 b0 = p4[u0 * 32 + lane];
        float4 a1 = h4[u1 * 32 + lane];
        float4 b1 = p4[u1 * 32 + lane];
        sa.x += a0.x + a1.x; sa.y += a0.y + a1.y; sa.z += a0.z + a1.z; sa.w += a0.w + a1.w;
        qa.x += b0.x + b1.x; qa.y += b0.y + b1.y; qa.z += b0.z + b1.z; qa.w += b0.w + b1.w;
    }
    if (i < i1) {
        int u0 = g_perm[i];
        float4 a0 = h4[u0 * 32 + lane];
        float4 b0 = p4[u0 * 32 + lane];
        sa.x += a0.x; sa.y += a0.y; sa.z += a0.z; sa.w += a0.w;
        qa.x += b0.x; qa.y += b0.y; qa.z += b0.z; qa.w += b0.w;
    }
    ((float4*)g_s)[gw * 32 + lane] = sa;
    ((float4*)g_q)[gw * 32 + lane] = qa;
}

// ---------------- weight fragment image prep ----------------
// W[k][n] row-major (n fast). Image float4 index t = (nt*8 + kp)*32 + lane:
//   n = nt*8 + lane>>2 ; k base = kp*16 + lane&3
//   words = W[k+0], W[k+4] (b0,b1 for ks=2kp), W[k+8], W[k+12] (ks=2kp+1), tf32-RN.
__global__ void k_prep(const float* w0, const float* w1, const float* w2,
                       const float* w3, const float* w4, const float* w5) {
    int mat = blockIdx.y;
    int t = blockIdx.x * 256 + threadIdx.x;    // 0..4095 per matrix
    if (t >= 4096) return;
    const float* srcs[6] = {w0, w1, w2, w3, w4, w5};
    const float* W = srcs[mat];
    int nt = t >> 8, kp = (t >> 5) & 7, lane = t & 31;
    int n = nt * 8 + (lane >> 2);
    int kb = kp * 16 + (lane & 3);
    uint4 v;
    v.x = totf32(W[(kb + 0)  * 128 + n]);
    v.y = totf32(W[(kb + 4)  * 128 + n]);
    v.z = totf32(W[(kb + 8)  * 128 + n]);
    v.w = totf32(W[(kb + 12) * 128 + n]);
    g_wimg[mat * 4096 + t] = v;
}

// ---------------- GEMM smem layout ----------------
#define SM_W1 0
#define SM_W2 65536
#define SM_X  131072
#define XP    132
#define SM_TOT (131072 + 128 * XP * 4)   // 198656

__device__ __forceinline__ void load_xA(float* sX, const float* __restrict__ x,
                                        int rowBase, int n, int tid) {
    const float4* s4 = (const float4*)x;
    #pragma unroll 4
    for (int i = tid; i < 4096; i += 256) {
        int m = i >> 5, c4 = i & 31;
        float4 v = (rowBase + m < n) ? s4[(size_t)(rowBase + m) * 32 + c4]
                                     : make_float4(0.f, 0.f, 0.f, 0.f);
        uint4 o;
        o.x = totf32(v.x); o.y = totf32(v.y); o.z = totf32(v.z); o.w = totf32(v.w);
        *(uint4*)(&sX[m * XP + c4 * 4]) = o;
    }
}

__device__ __forceinline__ void load_w2(char* sm, int mat1, int mat2, int tid) {
    const uint4* s1 = &g_wimg[mat1 * 4096];
    const uint4* s2 = &g_wimg[mat2 * 4096];
    uint4* d1 = (uint4*)(sm + SM_W1);
    uint4* d2 = (uint4*)(sm + SM_W2);
    for (int i = tid; i < 4096; i += 256) { d1[i] = s1[i]; d2[i] = s2[i]; }
}

// One 128x128x128 product into accumulators d[2][8][4].
// warp grid: wm = w>>1 (m 32-row slab), wn = w&1 (n 64-col slab)
__device__ __forceinline__ void product(const float* sX, const uint4* sW,
                                        float d[2][8][4], int wm, int wn, int lane) {
    int r0a = (wm * 2 + 0) * 16 + (lane >> 2);
    int r0b = (wm * 2 + 1) * 16 + (lane >> 2);
    int kl = lane & 3;
    for (int kp = 0; kp < 8; kp++) {
        uint32_t a[2][2][4];
        #pragma unroll
        for (int s = 0; s < 2; s++) {
            int k0 = (kp * 2 + s) * 8 + kl;
            a[0][s][0] = __float_as_uint(sX[r0a * XP + k0]);
            a[0][s][1] = __float_as_uint(sX[(r0a + 8) * XP + k0]);
            a[0][s][2] = __float_as_uint(sX[r0a * XP + k0 + 4]);
            a[0][s][3] = __float_as_uint(sX[(r0a + 8) * XP + k0 + 4]);
            a[1][s][0] = __float_as_uint(sX[r0b * XP + k0]);
            a[1][s][1] = __float_as_uint(sX[(r0b + 8) * XP + k0]);
            a[1][s][2] = __float_as_uint(sX[r0b * XP + k0 + 4]);
            a[1][s][3] = __float_as_uint(sX[(r0b + 8) * XP + k0 + 4]);
        }
        #pragma unroll
        for (int j = 0; j < 8; j++) {
            uint4 b = sW[((wn * 8 + j) * 8 + kp) * 32 + lane];
            mma8(d[0][j], a[0][0], b.x, b.y);
            mma8(d[1][j], a[1][0], b.x, b.y);
            mma8(d[0][j], a[0][1], b.z, b.w);
            mma8(d[1][j], a[1][1], b.z, b.w);
        }
    }
}

#define GEMM_PRE() \
    extern __shared__ char sm[]; \
    float* sX = (float*)(sm + SM_X); \
    const uint4* sW1 = (const uint4*)(sm + SM_W1); \
    const uint4* sW2 = (const uint4*)(sm + SM_W2); \
    int tid = threadIdx.x, w = tid >> 5, lane = tid & 31; \
    int wm = w >> 1, wn = w & 1; \
    int rowBase = blockIdx.x * 128; \
    (void)sW2;

#define ZERO_D(d) \
    _Pragma("unroll") for (int i = 0; i < 2; i++) \
    _Pragma("unroll") for (int j = 0; j < 8; j++) \
    _Pragma("unroll") for (int q = 0; q < 4; q++) d[i][j][q] = 0.f;

// zp = fsrc@wz + bz ; cp = fsrc@w + b
__global__ void __launch_bounds__(256) k_gemmA(const float* __restrict__ fsrc,
                                               const float* __restrict__ bz,
                                               const float* __restrict__ b, int n) {
    GEMM_PRE();
    load_w2(sm, 0, 1, tid);
    load_xA(sX, fsrc, rowBase, n, tid);
    __syncthreads();

    for (int which = 0; which < 2; which++) {
        float d[2][8][4];
        ZERO_D(d);
        product(sX, which ? sW2 : sW1, d, wm, wn, lane);
        const float* bias = which ? b : bz;
        float* outp = which ? g_cp : g_zp;
        #pragma unroll
        for (int i = 0; i < 2; i++) {
            int R = rowBase + (wm * 2 + i) * 16 + (lane >> 2);
            #pragma unroll
            for (int j = 0; j < 8; j++) {
                int C = wn * 64 + j * 8 + (lane & 3) * 2;
                float b0 = bias[C], b1 = bias[C + 1];
                if (R < n)
                    *(float2*)(outp + (size_t)R * 128 + C) =
                        make_float2(d[i][j][0] + b0, d[i][j][1] + b1);
                if (R + 8 < n)
                    *(float2*)(outp + (size_t)(R + 8) * 128 + C) =
                        make_float2(d[i][j][2] + b0, d[i][j][3] + b1);
            }
        }
    }
}

// p = sigmoid(fdst@wr + h@ur + br) * h
__global__ void __launch_bounds__(256) k_gemmB(const float* __restrict__ fdst,
                                               const float* __restrict__ h,
                                               const float* __restrict__ br, int n) {
    GEMM_PRE();
    load_w2(sm, 2, 3, tid);
    load_xA(sX, fdst, rowBase, n, tid);
    __syncthreads();

    float d[2][8][4];
    ZERO_D(d);
    product(sX, sW1, d, wm, wn, lane);
    __syncthreads();
    load_xA(sX, h, rowBase, n, tid);
    __syncthreads();
    product(sX, sW2, d, wm, wn, lane);

    #pragma unroll
    for (int i = 0; i < 2; i++) {
        int R = rowBase + (wm * 2 + i) * 16 + (lane >> 2);
        #pragma unroll
        for (int j = 0; j < 8; j++) {
            int C = wn * 64 + j * 8 + (lane & 3) * 2;
            float b0 = br[C], b1 = br[C + 1];
            if (R < n) {
                float2 hv = *(const float2*)(h + (size_t)R * 128 + C);
                *(float2*)(g_p + (size_t)R * 128 + C) =
                    make_float2(sigmoidf(d[i][j][0] + b0) * hv.x,
                                sigmoidf(d[i][j][1] + b1) * hv.y);
            }
            if (R + 8 < n) {
                float2 hv = *(const float2*)(h + (size_t)(R + 8) * 128 + C);
                *(float2*)(g_p + (size_t)(R + 8) * 128 + C) =
                    make_float2(sigmoidf(d[i][j][2] + b0) * hv.x,
                                sigmoidf(d[i][j][3] + b1) * hv.y);
            }
        }
    }
}

// z = sigmoid(zp + s@uz); ht = tanh(cp + q@u); out = (1-z)*s + z*ht
__global__ void __launch_bounds__(256) k_gemmC(float* __restrict__ out, int n) {
    GEMM_PRE();
    float* zbuf = (float*)(sm + SM_W1);   // reused after product1
    load_w2(sm, 4, 5, tid);
    load_xA(sX, g_s, rowBase, n, tid);
    __syncthreads();

    float d[2][8][4];
    ZERO_D(d);
    product(sX, sW1, d, wm, wn, lane);
    __syncthreads();   // everyone done reading sW1 & sX

    // z into zbuf (local row index), refill sX with q
    #pragma unroll
    for (int i = 0; i < 2; i++) {
        int Rl = (wm * 2 + i) * 16 + (lane >> 2);
        int R = rowBase + Rl;
        #pragma unroll
        for (int j = 0; j < 8; j++) {
            int C = wn * 64 + j * 8 + (lane & 3) * 2;
            float z0 = 0.f, z1 = 0.f, z2 = 0.f, z3 = 0.f;
            if (R < n) {
                float2 zp = *(const float2*)(g_zp + (size_t)R * 128 + C);
                z0 = sigmoidf(zp.x + d[i][j][0]);
                z1 = sigmoidf(zp.y + d[i][j][1]);
            }
            if (R + 8 < n) {
                float2 zp = *(const float2*)(g_zp + (size_t)(R + 8) * 128 + C);
                z2 = sigmoidf(zp.x + d[i][j][2]);
                z3 = sigmoidf(zp.y + d[i][j][3]);
            }
            *(float2*)(zbuf + Rl * 128 + C) = make_float2(z0, z1);
            *(float2*)(zbuf + (Rl + 8) * 128 + C) = make_float2(z2, z3);
        }
    }
    load_xA(sX, g_q, rowBase, n, tid);
    __syncthreads();

    ZERO_D(d);
    product(sX, sW2, d, wm, wn, lane);

    #pragma unroll
    for (int i = 0; i < 2; i++) {
        int Rl = (wm * 2 + i) * 16 + (lane >> 2);
        int R = rowBase + Rl;
        #pragma unroll
        for (int j = 0; j < 8; j++) {
            int C = wn * 64 + j * 8 + (lane & 3) * 2;
            if (R < n) {
                float2 cp = *(const float2*)(g_cp + (size_t)R * 128 + C);
                float2 sv = *(const float2*)(g_s + (size_t)R * 128 + C);
                float2 zv = *(const float2*)(zbuf + Rl * 128 + C);
                float t0 = tanh_fast(cp.x + d[i][j][0]);
                float t1 = tanh_fast(cp.y + d[i][j][1]);
                *(float2*)(out + (size_t)R * 128 + C) =
                    make_float2((1.f - zv.x) * sv.x + zv.x * t0,
                                (1.f - zv.y) * sv.y + zv.y * t1);
            }
            if (R + 8 < n) {
                float2 cp = *(const float2*)(g_cp + (size_t)(R + 8) * 128 + C);
                float2 sv = *(const float2*)(g_s + (size_t)(R + 8) * 128 + C);
                float2 zv = *(const float2*)(zbuf + (Rl + 8) * 128 + C);
                float t0 = tanh_fast(cp.x + d[i][j][2]);
                float t1 = tanh_fast(cp.y + d[i][j][3]);
                *(float2*)(out + (size_t)(R + 8) * 128 + C) =
                    make_float2((1.f - zv.x) * sv.x + zv.x * t0,
                                (1.f - zv.y) * sv.y + zv.y * t1);
            }
        }
    }
}

// ---------------- launch ----------------
extern "C" void kernel_launch(void* const* d_in, const int* in_sizes, int n_in,
                              void* d_out, int out_size)
{
    const float* h    = (const float*)d_in[0];
    const float* fsrc = (const float*)d_in[1];
    const float* fdst = (const float*)d_in[2];
    const int*   src  = (const int*)d_in[3];
    const int*   dst  = (const int*)d_in[4];
    const float* wz   = (const float*)d_in[5];
    const float* uz   = (const float*)d_in[6];
    const float* bz   = (const float*)d_in[7];
    const float* wr   = (const float*)d_in[8];
    const float* ur   = (const float*)d_in[9];
    const float* br   = (const float*)d_in[10];
    const float* w    = (const float*)d_in[11];
    const float* u    = (const float*)d_in[12];
    const float* b    = (const float*)d_in[13];
    float* out = (float*)d_out;

    int n = in_sizes[0] / 128;
    int e = in_sizes[3];
    if (n > NMAX || e > EMAX) return;

    cudaFuncSetAttribute(k_gemmA, cudaFuncAttributeMaxDynamicSharedMemorySize, SM_TOT);
    cudaFuncSetAttribute(k_gemmB, cudaFuncAttributeMaxDynamicSharedMemorySize, SM_TOT);
    cudaFuncSetAttribute(k_gemmC, cudaFuncAttributeMaxDynamicSharedMemorySize, SM_TOT);

    int gemmBlocks = (n + 127) / 128;

    k_prep<<<dim3(16, 6), 256>>>(wz, w, wr, ur, uz, u);
    k_zero<<<(n + 255) / 256, 256>>>(n);
    k_hist<<<(e + 255) / 256, 256>>>(dst, e);
    k_scan<<<1, 1024>>>(n, e);
    k_scatter<<<(e + 255) / 256, 256>>>(src, dst, e);
    k_gemmB<<<gemmBlocks, 256, SM_TOT>>>(fdst, h, br, n);
    k_gemmA<<<gemmBlocks, 256, SM_TOT>>>(fsrc, bz, b, n);
    k_reduce<<<(n + 7) / 8, 256>>>(h, n);
    k_gemmC<<<gemmBlocks, 256, SM_TOT>>>(out, n);
}

// round 6
// speedup vs baseline: 2.7717x; 1.2282x over previous
#include <cuda_runtime.h>
#include <cstdint>

#define NMAX 100000
#define EMAX 1600000

// ---------------- scratch ----------------
__device__ float g_p [NMAX * 128];
__device__ float g_zp[NMAX * 128];
__device__ float g_cp[NMAX * 128];
__device__ float g_s [NMAX * 128];
__device__ float g_q [NMAX * 128];
__device__ int   g_cnt[NMAX];
__device__ int   g_off[NMAX + 1];
__device__ int   g_cur[NMAX];
__device__ int   g_perm[EMAX];
__device__ int   g_bsum[128];
__device__ int   g_bpre[128];
__device__ uint4 g_wimg[6 * 4096];   // 6 weight images, 64KB each, B-fragment order

__device__ __forceinline__ float sigmoidf(float x) { return 1.0f / (1.0f + __expf(-x)); }
__device__ __forceinline__ float tanh_fast(float x) {
    return __fdividef(2.0f, 1.0f + __expf(-2.0f * x)) - 1.0f;
}
__device__ __forceinline__ uint32_t totf32(float f) {
    uint32_t r; asm("cvt.rna.tf32.f32 %0,%1;" : "=r"(r) : "f"(f)); return r;
}

// ---------------- mma.sync m16n8k8 tf32 ----------------
__device__ __forceinline__ void mma8(float* d, const uint32_t* a, uint32_t b0, uint32_t b1) {
    asm("mma.sync.aligned.m16n8k8.row.col.f32.tf32.tf32.f32 "
        "{%0,%1,%2,%3},{%4,%5,%6,%7},{%8,%9},{%0,%1,%2,%3};"
        : "+f"(d[0]), "+f"(d[1]), "+f"(d[2]), "+f"(d[3])
        : "r"(a[0]), "r"(a[1]), "r"(a[2]), "r"(a[3]), "r"(b0), "r"(b1));
}

// ---------------- CSR build ----------------
__global__ void k_zero(int n) {
    int i = blockIdx.x * blockDim.x + threadIdx.x;
    if (i < n) g_cnt[i] = 0;
}
__global__ void k_hist(const int* __restrict__ dst, int e) {
    int i = blockIdx.x * blockDim.x + threadIdx.x;
    if (i < e) atomicAdd(&g_cnt[dst[i]], 1);
}

// phase 1: block-local scan of 1024 counters, store local exclusive prefix in
// g_off, block total in g_bsum.
__global__ void k_part(int n) {
    __shared__ int sm[1024];
    int b = blockIdx.x, t = threadIdx.x;
    int idx = b * 1024 + t;
    int v = (idx < n) ? g_cnt[idx] : 0;
    sm[t] = v;
    __syncthreads();
    #pragma unroll
    for (int off = 1; off < 1024; off <<= 1) {
        int x = (t >= off) ? sm[t - off] : 0;
        __syncthreads();
        sm[t] += x;
        __syncthreads();
    }
    if (idx < n) g_off[idx] = sm[t] - v;   // local exclusive
    if (t == 1023) g_bsum[b] = sm[t];
}

// phase 2: one small block scans the per-block totals (exclusive)
__global__ void k_scanb(int nb) {
    __shared__ int sm[128];
    int t = threadIdx.x;
    int v = (t < nb) ? g_bsum[t] : 0;
    sm[t] = v;
    __syncthreads();
    #pragma unroll
    for (int off = 1; off < 128; off <<= 1) {
        int x = (t >= off) ? sm[t - off] : 0;
        __syncthreads();
        sm[t] += x;
        __syncthreads();
    }
    if (t < nb) g_bpre[t] = sm[t] - v;
}

// phase 3: add block prefixes, init cursors, set sentinel
__global__ void k_add(int n, int e) {
    int idx = blockIdx.x * blockDim.x + threadIdx.x;
    if (idx < n) {
        int o = g_off[idx] + g_bpre[idx >> 10];
        g_off[idx] = o;
        g_cur[idx] = o;
    }
    if (idx == 0) g_off[n] = e;
}

__global__ void k_scatter(const int* __restrict__ src, const int* __restrict__ dst, int e) {
    int i = blockIdx.x * blockDim.x + threadIdx.x;
    if (i < e) {
        int d = dst[i];
        int pos = atomicAdd(&g_cur[d], 1);
        g_perm[pos] = src[i];
    }
}

// ---------------- segment reduce: warp per node ----------------
__global__ void k_reduce(const float* __restrict__ h, int n) {
    int gw = (blockIdx.x * blockDim.x + threadIdx.x) >> 5;
    int lane = threadIdx.x & 31;
    if (gw >= n) return;
    int i0 = g_off[gw], i1 = g_off[gw + 1];
    const float4* h4 = (const float4*)h;
    const float4* p4 = (const float4*)g_p;
    float4 sa = make_float4(0.f, 0.f, 0.f, 0.f);
    float4 qa = make_float4(0.f, 0.f, 0.f, 0.f);
    int i = i0;
    for (; i + 1 < i1; i += 2) {
        int u0 = g_perm[i], u1 = g_perm[i + 1];
        float4 a0 = h4[u0 * 32 + lane];
        float4 b0 = p4[u0 * 32 + lane];
        float4 a1 = h4[u1 * 32 + lane];
        float4 b1 = p4[u1 * 32 + lane];
        sa.x += a0.x + a1.x; sa.y += a0.y + a1.y; sa.z += a0.z + a1.z; sa.w += a0.w + a1.w;
        qa.x += b0.x + b1.x; qa.y += b0.y + b1.y; qa.z += b0.z + b1.z; qa.w += b0.w + b1.w;
    }
    if (i < i1) {
        int u0 = g_perm[i];
        float4 a0 = h4[u0 * 32 + lane];
        float4 b0 = p4[u0 * 32 + lane];
        sa.x += a0.x; sa.y += a0.y; sa.z += a0.z; sa.w += a0.w;
        qa.x += b0.x; qa.y += b0.y; qa.z += b0.z; qa.w += b0.w;
    }
    ((float4*)g_s)[gw * 32 + lane] = sa;
    ((float4*)g_q)[gw * 32 + lane] = qa;
}

// ---------------- weight fragment image prep ----------------
__global__ void k_prep(const float* w0, const float* w1, const float* w2,
                       const float* w3, const float* w4, const float* w5) {
    int mat = blockIdx.y;
    int t = blockIdx.x * 256 + threadIdx.x;    // 0..4095 per matrix
    if (t >= 4096) return;
    const float* srcs[6] = {w0, w1, w2, w3, w4, w5};
    const float* W = srcs[mat];
    int nt = t >> 8, kp = (t >> 5) & 7, lane = t & 31;
    int n = nt * 8 + (lane >> 2);
    int kb = kp * 16 + (lane & 3);
    uint4 v;
    v.x = totf32(W[(kb + 0)  * 128 + n]);
    v.y = totf32(W[(kb + 4)  * 128 + n]);
    v.z = totf32(W[(kb + 8)  * 128 + n]);
    v.w = totf32(W[(kb + 12) * 128 + n]);
    g_wimg[mat * 4096 + t] = v;
}

// ---------------- GEMM smem layout ----------------
#define SM_W1 0
#define SM_W2 65536
#define SM_X  131072
#define XP    132
#define SM_TOT (131072 + 128 * XP * 4)   // 198656

__device__ __forceinline__ void load_xA(float* sX, const float* __restrict__ x,
                                        int rowBase, int n, int tid) {
    const float4* s4 = (const float4*)x;
    #pragma unroll 4
    for (int i = tid; i < 4096; i += 256) {
        int m = i >> 5, c4 = i & 31;
        float4 v = (rowBase + m < n) ? s4[(size_t)(rowBase + m) * 32 + c4]
                                     : make_float4(0.f, 0.f, 0.f, 0.f);
        uint4 o;
        o.x = totf32(v.x); o.y = totf32(v.y); o.z = totf32(v.z); o.w = totf32(v.w);
        *(uint4*)(&sX[m * XP + c4 * 4]) = o;
    }
}

__device__ __forceinline__ void load_w2(char* sm, int mat1, int mat2, int tid) {
    const uint4* s1 = &g_wimg[mat1 * 4096];
    const uint4* s2 = &g_wimg[mat2 * 4096];
    uint4* d1 = (uint4*)(sm + SM_W1);
    uint4* d2 = (uint4*)(sm + SM_W2);
    for (int i = tid; i < 4096; i += 256) { d1[i] = s1[i]; d2[i] = s2[i]; }
}

// One 128x128x128 product into accumulators d[2][8][4].
__device__ __forceinline__ void product(const float* sX, const uint4* sW,
                                        float d[2][8][4], int wm, int wn, int lane) {
    int r0a = (wm * 2 + 0) * 16 + (lane >> 2);
    int r0b = (wm * 2 + 1) * 16 + (lane >> 2);
    int kl = lane & 3;
    for (int kp = 0; kp < 8; kp++) {
        uint32_t a[2][2][4];
        #pragma unroll
        for (int s = 0; s < 2; s++) {
            int k0 = (kp * 2 + s) * 8 + kl;
            a[0][s][0] = __float_as_uint(sX[r0a * XP + k0]);
            a[0][s][1] = __float_as_uint(sX[(r0a + 8) * XP + k0]);
            a[0][s][2] = __float_as_uint(sX[r0a * XP + k0 + 4]);
            a[0][s][3] = __float_as_uint(sX[(r0a + 8) * XP + k0 + 4]);
            a[1][s][0] = __float_as_uint(sX[r0b * XP + k0]);
            a[1][s][1] = __float_as_uint(sX[(r0b + 8) * XP + k0]);
            a[1][s][2] = __float_as_uint(sX[r0b * XP + k0 + 4]);
            a[1][s][3] = __float_as_uint(sX[(r0b + 8) * XP + k0 + 4]);
        }
        #pragma unroll
        for (int j = 0; j < 8; j++) {
            uint4 b = sW[((wn * 8 + j) * 8 + kp) * 32 + lane];
            mma8(d[0][j], a[0][0], b.x, b.y);
            mma8(d[1][j], a[1][0], b.x, b.y);
            mma8(d[0][j], a[0][1], b.z, b.w);
            mma8(d[1][j], a[1][1], b.z, b.w);
        }
    }
}

#define GEMM_PRE() \
    extern __shared__ char sm[]; \
    float* sX = (float*)(sm + SM_X); \
    const uint4* sW1 = (const uint4*)(sm + SM_W1); \
    const uint4* sW2 = (const uint4*)(sm + SM_W2); \
    int tid = threadIdx.x, w = tid >> 5, lane = tid & 31; \
    int wm = w >> 1, wn = w & 1; \
    int rowBase = blockIdx.x * 128; \
    (void)sW2;

#define ZERO_D(d) \
    _Pragma("unroll") for (int i = 0; i < 2; i++) \
    _Pragma("unroll") for (int j = 0; j < 8; j++) \
    _Pragma("unroll") for (int q = 0; q < 4; q++) d[i][j][q] = 0.f;

// zp = fsrc@wz + bz ; cp = fsrc@w + b
__global__ void __launch_bounds__(256) k_gemmA(const float* __restrict__ fsrc,
                                               const float* __restrict__ bz,
                                               const float* __restrict__ b, int n) {
    GEMM_PRE();
    load_w2(sm, 0, 1, tid);
    load_xA(sX, fsrc, rowBase, n, tid);
    __syncthreads();

    for (int which = 0; which < 2; which++) {
        float d[2][8][4];
        ZERO_D(d);
        product(sX, which ? sW2 : sW1, d, wm, wn, lane);
        const float* bias = which ? b : bz;
        float* outp = which ? g_cp : g_zp;
        #pragma unroll
        for (int i = 0; i < 2; i++) {
            int R = rowBase + (wm * 2 + i) * 16 + (lane >> 2);
            #pragma unroll
            for (int j = 0; j < 8; j++) {
                int C = wn * 64 + j * 8 + (lane & 3) * 2;
                float b0 = bias[C], b1 = bias[C + 1];
                if (R < n)
                    *(float2*)(outp + (size_t)R * 128 + C) =
                        make_float2(d[i][j][0] + b0, d[i][j][1] + b1);
                if (R + 8 < n)
                    *(float2*)(outp + (size_t)(R + 8) * 128 + C) =
                        make_float2(d[i][j][2] + b0, d[i][j][3] + b1);
            }
        }
    }
}

// p = sigmoid(fdst@wr + h@ur + br) * h
__global__ void __launch_bounds__(256) k_gemmB(const float* __restrict__ fdst,
                                               const float* __restrict__ h,
                                               const float* __restrict__ br, int n) {
    GEMM_PRE();
    load_w2(sm, 2, 3, tid);
    load_xA(sX, fdst, rowBase, n, tid);
    __syncthreads();

    float d[2][8][4];
    ZERO_D(d);
    product(sX, sW1, d, wm, wn, lane);
    __syncthreads();
    load_xA(sX, h, rowBase, n, tid);
    __syncthreads();
    product(sX, sW2, d, wm, wn, lane);

    #pragma unroll
    for (int i = 0; i < 2; i++) {
        int R = rowBase + (wm * 2 + i) * 16 + (lane >> 2);
        #pragma unroll
        for (int j = 0; j < 8; j++) {
            int C = wn * 64 + j * 8 + (lane & 3) * 2;
            float b0 = br[C], b1 = br[C + 1];
            if (R < n) {
                float2 hv = *(const float2*)(h + (size_t)R * 128 + C);
                *(float2*)(g_p + (size_t)R * 128 + C) =
                    make_float2(sigmoidf(d[i][j][0] + b0) * hv.x,
                                sigmoidf(d[i][j][1] + b1) * hv.y);
            }
            if (R + 8 < n) {
                float2 hv = *(const float2*)(h + (size_t)(R + 8) * 128 + C);
                *(float2*)(g_p + (size_t)(R + 8) * 128 + C) =
                    make_float2(sigmoidf(d[i][j][2] + b0) * hv.x,
                                sigmoidf(d[i][j][3] + b1) * hv.y);
            }
        }
    }
}

// z = sigmoid(zp + s@uz); ht = tanh(cp + q@u); out = (1-z)*s + z*ht
__global__ void __launch_bounds__(256) k_gemmC(float* __restrict__ out, int n) {
    GEMM_PRE();
    float* zbuf = (float*)(sm + SM_W1);   // reused after product1
    load_w2(sm, 4, 5, tid);
    load_xA(sX, g_s, rowBase, n, tid);
    __syncthreads();

    float d[2][8][4];
    ZERO_D(d);
    product(sX, sW1, d, wm, wn, lane);
    __syncthreads();   // everyone done reading sW1 & sX

    #pragma unroll
    for (int i = 0; i < 2; i++) {
        int Rl = (wm * 2 + i) * 16 + (lane >> 2);
        int R = rowBase + Rl;
        #pragma unroll
        for (int j = 0; j < 8; j++) {
            int C = wn * 64 + j * 8 + (lane & 3) * 2;
            float z0 = 0.f, z1 = 0.f, z2 = 0.f, z3 = 0.f;
            if (R < n) {
                float2 zp = *(const float2*)(g_zp + (size_t)R * 128 + C);
                z0 = sigmoidf(zp.x + d[i][j][0]);
                z1 = sigmoidf(zp.y + d[i][j][1]);
            }
            if (R + 8 < n) {
                float2 zp = *(const float2*)(g_zp + (size_t)(R + 8) * 128 + C);
                z2 = sigmoidf(zp.x + d[i][j][2]);
                z3 = sigmoidf(zp.y + d[i][j][3]);
            }
            *(float2*)(zbuf + Rl * 128 + C) = make_float2(z0, z1);
            *(float2*)(zbuf + (Rl + 8) * 128 + C) = make_float2(z2, z3);
        }
    }
    load_xA(sX, g_q, rowBase, n, tid);
    __syncthreads();

    ZERO_D(d);
    product(sX, sW2, d, wm, wn, lane);

    #pragma unroll
    for (int i = 0; i < 2; i++) {
        int Rl = (wm * 2 + i) * 16 + (lane >> 2);
        int R = rowBase + Rl;
        #pragma unroll
        for (int j = 0; j < 8; j++) {
            int C = wn * 64 + j * 8 + (lane & 3) * 2;
            if (R < n) {
                float2 cp = *(const float2*)(g_cp + (size_t)R * 128 + C);
                float2 sv = *(const float2*)(g_s + (size_t)R * 128 + C);
                float2 zv = *(const float2*)(zbuf + Rl * 128 + C);
                float t0 = tanh_fast(cp.x + d[i][j][0]);
                float t1 = tanh_fast(cp.y + d[i][j][1]);
                *(float2*)(out + (size_t)R * 128 + C) =
                    make_float2((1.f - zv.x) * sv.x + zv.x * t0,
                                (1.f - zv.y) * sv.y + zv.y * t1);
            }
            if (R + 8 < n) {
                float2 cp = *(const float2*)(g_cp + (size_t)(R + 8) * 128 + C);
                float2 sv = *(const float2*)(g_s + (size_t)(R + 8) * 128 + C);
                float2 zv = *(const float2*)(zbuf + (Rl + 8) * 128 + C);
                float t0 = tanh_fast(cp.x + d[i][j][2]);
                float t1 = tanh_fast(cp.y + d[i][j][3]);
                *(float2*)(out + (size_t)(R + 8) * 128 + C) =
                    make_float2((1.f - zv.x) * sv.x + zv.x * t0,
                                (1.f - zv.y) * sv.y + zv.y * t1);
            }
        }
    }
}

// ---------------- launch ----------------
extern "C" void kernel_launch(void* const* d_in, const int* in_sizes, int n_in,
                              void* d_out, int out_size)
{
    const float* h    = (const float*)d_in[0];
    const float* fsrc = (const float*)d_in[1];
    const float* fdst = (const float*)d_in[2];
    const int*   src  = (const int*)d_in[3];
    const int*   dst  = (const int*)d_in[4];
    const float* wz   = (const float*)d_in[5];
    const float* uz   = (const float*)d_in[6];
    const float* bz   = (const float*)d_in[7];
    const float* wr   = (const float*)d_in[8];
    const float* ur   = (const float*)d_in[9];
    const float* br   = (const float*)d_in[10];
    const float* w    = (const float*)d_in[11];
    const float* u    = (const float*)d_in[12];
    const float* b    = (const float*)d_in[13];
    float* out = (float*)d_out;

    int n = in_sizes[0] / 128;
    int e = in_sizes[3];
    if (n > NMAX || e > EMAX) return;

    cudaFuncSetAttribute(k_gemmA, cudaFuncAttributeMaxDynamicSharedMemorySize, SM_TOT);
    cudaFuncSetAttribute(k_gemmB, cudaFuncAttributeMaxDynamicSharedMemorySize, SM_TOT);
    cudaFuncSetAttribute(k_gemmC, cudaFuncAttributeMaxDynamicSharedMemorySize, SM_TOT);

    int gemmBlocks = (n + 127) / 128;
    int nb = (n + 1023) / 1024;          // scan blocks (<=128)

    k_prep<<<dim3(16, 6), 256>>>(wz, w, wr, ur, uz, u);
    k_zero<<<(n + 255) / 256, 256>>>(n);
    k_hist<<<(e + 255) / 256, 256>>>(dst, e);
    k_part<<<nb, 1024>>>(n);
    k_scanb<<<1, 128>>>(nb);
    k_add<<<(n + 1023) / 1024, 1024>>>(n, e);
    k_scatter<<<(e + 255) / 256, 256>>>(src, dst, e);
    k_gemmB<<<gemmBlocks, 256, SM_TOT>>>(fdst, h, br, n);
    k_gemmA<<<gemmBlocks, 256, SM_TOT>>>(fsrc, bz, b, n);
    k_reduce<<<(n + 7) / 8, 256>>>(h, n);
    k_gemmC<<<gemmBlocks, 256, SM_TOT>>>(out, n);
}

// round 7
// speedup vs baseline: 3.9104x; 1.4108x over previous
#include <cuda_runtime.h>
#include <cstdint>

#define NMAX 100000
#define EMAX 1600000

// ---------------- scratch ----------------
__device__ float g_p [NMAX * 128];
__device__ float g_zp[NMAX * 128];
__device__ float g_cp[NMAX * 128];
__device__ float g_s [NMAX * 128];
__device__ float g_q [NMAX * 128];
__device__ int   g_cnt[NMAX];
__device__ int   g_off[NMAX + 1];
__device__ int   g_cur[NMAX];
__device__ int   g_perm[EMAX];
__device__ int   g_bsum[128];
__device__ int   g_bpre[128];
__device__ uint4 g_wimg[6 * 4096];   // 6 weight images, 64KB each, B-fragment order

__device__ __forceinline__ float sigmoidf(float x) { return 1.0f / (1.0f + __expf(-x)); }
__device__ __forceinline__ float tanh_fast(float x) {
    return __fdividef(2.0f, 1.0f + __expf(-2.0f * x)) - 1.0f;
}
__device__ __forceinline__ uint32_t totf32(float f) {
    uint32_t r; asm("cvt.rna.tf32.f32 %0,%1;" : "=r"(r) : "f"(f)); return r;
}

// ---------------- mma.sync m16n8k8 tf32 ----------------
__device__ __forceinline__ void mma8(float* d, const uint32_t* a, uint32_t b0, uint32_t b1) {
    asm("mma.sync.aligned.m16n8k8.row.col.f32.tf32.tf32.f32 "
        "{%0,%1,%2,%3},{%4,%5,%6,%7},{%8,%9},{%0,%1,%2,%3};"
        : "+f"(d[0]), "+f"(d[1]), "+f"(d[2]), "+f"(d[3])
        : "r"(a[0]), "r"(a[1]), "r"(a[2]), "r"(a[3]), "r"(b0), "r"(b1));
}

// ---------------- CSR build ----------------
__global__ void k_zero(int n) {
    int i = blockIdx.x * blockDim.x + threadIdx.x;
    if (i < n) g_cnt[i] = 0;
}
__global__ void k_hist(const int* __restrict__ dst, int e) {
    int i = blockIdx.x * blockDim.x + threadIdx.x;
    if (i < e) atomicAdd(&g_cnt[dst[i]], 1);
}

__global__ void k_part(int n) {
    __shared__ int sm[1024];
    int b = blockIdx.x, t = threadIdx.x;
    int idx = b * 1024 + t;
    int v = (idx < n) ? g_cnt[idx] : 0;
    sm[t] = v;
    __syncthreads();
    #pragma unroll
    for (int off = 1; off < 1024; off <<= 1) {
        int x = (t >= off) ? sm[t - off] : 0;
        __syncthreads();
        sm[t] += x;
        __syncthreads();
    }
    if (idx < n) g_off[idx] = sm[t] - v;   // local exclusive
    if (t == 1023) g_bsum[b] = sm[t];
}

__global__ void k_scanb(int nb) {
    __shared__ int sm[128];
    int t = threadIdx.x;
    int v = (t < nb) ? g_bsum[t] : 0;
    sm[t] = v;
    __syncthreads();
    #pragma unroll
    for (int off = 1; off < 128; off <<= 1) {
        int x = (t >= off) ? sm[t - off] : 0;
        __syncthreads();
        sm[t] += x;
        __syncthreads();
    }
    if (t < nb) g_bpre[t] = sm[t] - v;
}

__global__ void k_add(int n, int e) {
    int idx = blockIdx.x * blockDim.x + threadIdx.x;
    if (idx < n) {
        int o = g_off[idx] + g_bpre[idx >> 10];
        g_off[idx] = o;
        g_cur[idx] = o;
    }
    if (idx == 0) g_off[n] = e;
}

__global__ void k_scatter(const int* __restrict__ src, const int* __restrict__ dst, int e) {
    int i = blockIdx.x * blockDim.x + threadIdx.x;
    if (i < e) {
        int d = dst[i];
        int pos = atomicAdd(&g_cur[d], 1);
        g_perm[pos] = src[i];
    }
}

// ---------------- segment reduce: warp per node ----------------
__global__ void k_reduce(const float* __restrict__ h, int n) {
    int gw = (blockIdx.x * blockDim.x + threadIdx.x) >> 5;
    int lane = threadIdx.x & 31;
    if (gw >= n) return;
    int i0 = g_off[gw], i1 = g_off[gw + 1];
    const float4* h4 = (const float4*)h;
    const float4* p4 = (const float4*)g_p;
    float4 sa = make_float4(0.f, 0.f, 0.f, 0.f);
    float4 qa = make_float4(0.f, 0.f, 0.f, 0.f);
    int i = i0;
    for (; i + 1 < i1; i += 2) {
        int u0 = g_perm[i], u1 = g_perm[i + 1];
        float4 a0 = h4[u0 * 32 + lane];
        float4 b0 = p4[u0 * 32 + lane];
        float4 a1 = h4[u1 * 32 + lane];
        float4 b1 = p4[u1 * 32 + lane];
        sa.x += a0.x + a1.x; sa.y += a0.y + a1.y; sa.z += a0.z + a1.z; sa.w += a0.w + a1.w;
        qa.x += b0.x + b1.x; qa.y += b0.y + b1.y; qa.z += b0.z + b1.z; qa.w += b0.w + b1.w;
    }
    if (i < i1) {
        int u0 = g_perm[i];
        float4 a0 = h4[u0 * 32 + lane];
        float4 b0 = p4[u0 * 32 + lane];
        sa.x += a0.x; sa.y += a0.y; sa.z += a0.z; sa.w += a0.w;
        qa.x += b0.x; qa.y += b0.y; qa.z += b0.z; qa.w += b0.w;
    }
    ((float4*)g_s)[gw * 32 + lane] = sa;
    ((float4*)g_q)[gw * 32 + lane] = qa;
}

// ---------------- weight fragment image prep ----------------
__global__ void k_prep(const float* w0, const float* w1, const float* w2,
                       const float* w3, const float* w4, const float* w5) {
    int mat = blockIdx.y;
    int t = blockIdx.x * 256 + threadIdx.x;    // 0..4095 per matrix
    if (t >= 4096) return;
    const float* srcs[6] = {w0, w1, w2, w3, w4, w5};
    const float* W = srcs[mat];
    int nt = t >> 8, kp = (t >> 5) & 7, lane = t & 31;
    int n = nt * 8 + (lane >> 2);
    int kb = kp * 16 + (lane & 3);
    uint4 v;
    v.x = totf32(W[(kb + 0)  * 128 + n]);
    v.y = totf32(W[(kb + 4)  * 128 + n]);
    v.z = totf32(W[(kb + 8)  * 128 + n]);
    v.w = totf32(W[(kb + 12) * 128 + n]);
    g_wimg[mat * 4096 + t] = v;
}

// ---------------- GEMM: smem holds only the x tile ----------------
#define XP    132
#define SM_TOT (128 * XP * 4)   // 67584 -> 2+ blocks/SM

__device__ __forceinline__ void load_xA(float* sX, const float* __restrict__ x,
                                        int rowBase, int n, int tid) {
    const float4* s4 = (const float4*)x;
    #pragma unroll 4
    for (int i = tid; i < 4096; i += 256) {
        int m = i >> 5, c4 = i & 31;
        float4 v = (rowBase + m < n) ? s4[(size_t)(rowBase + m) * 32 + c4]
                                     : make_float4(0.f, 0.f, 0.f, 0.f);
        uint4 o;
        o.x = totf32(v.x); o.y = totf32(v.y); o.z = totf32(v.z); o.w = totf32(v.w);
        *(uint4*)(&sX[m * XP + c4 * 4]) = o;
    }
}

// One 128x128x128 product; B fragments streamed from L2 (g_wimg) via LDG.
__device__ __forceinline__ void product(const float* sX, const uint4* __restrict__ gW,
                                        float d[2][8][4], int wm, int wn, int lane) {
    int r0a = (wm * 2 + 0) * 16 + (lane >> 2);
    int r0b = (wm * 2 + 1) * 16 + (lane >> 2);
    int kl = lane & 3;
    for (int kp = 0; kp < 8; kp++) {
        uint32_t a[2][2][4];
        #pragma unroll
        for (int s = 0; s < 2; s++) {
            int k0 = (kp * 2 + s) * 8 + kl;
            a[0][s][0] = __float_as_uint(sX[r0a * XP + k0]);
            a[0][s][1] = __float_as_uint(sX[(r0a + 8) * XP + k0]);
            a[0][s][2] = __float_as_uint(sX[r0a * XP + k0 + 4]);
            a[0][s][3] = __float_as_uint(sX[(r0a + 8) * XP + k0 + 4]);
            a[1][s][0] = __float_as_uint(sX[r0b * XP + k0]);
            a[1][s][1] = __float_as_uint(sX[(r0b + 8) * XP + k0]);
            a[1][s][2] = __float_as_uint(sX[r0b * XP + k0 + 4]);
            a[1][s][3] = __float_as_uint(sX[(r0b + 8) * XP + k0 + 4]);
        }
        #pragma unroll
        for (int j = 0; j < 8; j++) {
            uint4 b = __ldg(&gW[((wn * 8 + j) * 8 + kp) * 32 + lane]);
            mma8(d[0][j], a[0][0], b.x, b.y);
            mma8(d[1][j], a[1][0], b.x, b.y);
            mma8(d[0][j], a[0][1], b.z, b.w);
            mma8(d[1][j], a[1][1], b.z, b.w);
        }
    }
}

#define GEMM_PRE() \
    extern __shared__ char sm[]; \
    float* sX = (float*)sm; \
    int tid = threadIdx.x, w = tid >> 5, lane = tid & 31; \
    int wm = w >> 1, wn = w & 1; \
    int rowBase = blockIdx.x * 128;

#define ZERO_D(d) \
    _Pragma("unroll") for (int i = 0; i < 2; i++) \
    _Pragma("unroll") for (int j = 0; j < 8; j++) \
    _Pragma("unroll") for (int q = 0; q < 4; q++) d[i][j][q] = 0.f;

// zp = fsrc@wz + bz ; cp = fsrc@w + b
__global__ void __launch_bounds__(256, 2) k_gemmA(const float* __restrict__ fsrc,
                                                  const float* __restrict__ bz,
                                                  const float* __restrict__ b, int n) {
    GEMM_PRE();
    load_xA(sX, fsrc, rowBase, n, tid);
    __syncthreads();

    for (int which = 0; which < 2; which++) {
        float d[2][8][4];
        ZERO_D(d);
        product(sX, &g_wimg[(which ? 1 : 0) * 4096], d, wm, wn, lane);
        const float* bias = which ? b : bz;
        float* outp = which ? g_cp : g_zp;
        #pragma unroll
        for (int i = 0; i < 2; i++) {
            int R = rowBase + (wm * 2 + i) * 16 + (lane >> 2);
            #pragma unroll
            for (int j = 0; j < 8; j++) {
                int C = wn * 64 + j * 8 + (lane & 3) * 2;
                float b0 = bias[C], b1 = bias[C + 1];
                if (R < n)
                    *(float2*)(outp + (size_t)R * 128 + C) =
                        make_float2(d[i][j][0] + b0, d[i][j][1] + b1);
                if (R + 8 < n)
                    *(float2*)(outp + (size_t)(R + 8) * 128 + C) =
                        make_float2(d[i][j][2] + b0, d[i][j][3] + b1);
            }
        }
    }
}

// p = sigmoid(fdst@wr + h@ur + br) * h
__global__ void __launch_bounds__(256, 2) k_gemmB(const float* __restrict__ fdst,
                                                  const float* __restrict__ h,
                                                  const float* __restrict__ br, int n) {
    GEMM_PRE();
    load_xA(sX, fdst, rowBase, n, tid);
    __syncthreads();

    float d[2][8][4];
    ZERO_D(d);
    product(sX, &g_wimg[2 * 4096], d, wm, wn, lane);
    __syncthreads();
    load_xA(sX, h, rowBase, n, tid);
    __syncthreads();
    product(sX, &g_wimg[3 * 4096], d, wm, wn, lane);

    #pragma unroll
    for (int i = 0; i < 2; i++) {
        int R = rowBase + (wm * 2 + i) * 16 + (lane >> 2);
        #pragma unroll
        for (int j = 0; j < 8; j++) {
            int C = wn * 64 + j * 8 + (lane & 3) * 2;
            float b0 = br[C], b1 = br[C + 1];
            if (R < n) {
                float2 hv = *(const float2*)(h + (size_t)R * 128 + C);
                *(float2*)(g_p + (size_t)R * 128 + C) =
                    make_float2(sigmoidf(d[i][j][0] + b0) * hv.x,
                                sigmoidf(d[i][j][1] + b1) * hv.y);
            }
            if (R + 8 < n) {
                float2 hv = *(const float2*)(h + (size_t)(R + 8) * 128 + C);
                *(float2*)(g_p + (size_t)(R + 8) * 128 + C) =
                    make_float2(sigmoidf(d[i][j][2] + b0) * hv.x,
                                sigmoidf(d[i][j][3] + b1) * hv.y);
            }
        }
    }
}

// z = sigmoid(zp + s@uz); ht = tanh(cp + q@u); out = (1-z)*s + z*ht
// z is staged in-place over g_zp (each thread re-reads its own writes).
__global__ void __launch_bounds__(256, 2) k_gemmC(float* __restrict__ out, int n) {
    GEMM_PRE();
    load_xA(sX, g_s, rowBase, n, tid);
    __syncthreads();

    float d[2][8][4];
    ZERO_D(d);
    product(sX, &g_wimg[4 * 4096], d, wm, wn, lane);
    __syncthreads();

    // z -> overwrite g_zp (same addresses this thread reads later)
    #pragma unroll
    for (int i = 0; i < 2; i++) {
        int R = rowBase + (wm * 2 + i) * 16 + (lane >> 2);
        #pragma unroll
        for (int j = 0; j < 8; j++) {
            int C = wn * 64 + j * 8 + (lane & 3) * 2;
            if (R < n) {
                float2 zp = *(const float2*)(g_zp + (size_t)R * 128 + C);
                *(float2*)(g_zp + (size_t)R * 128 + C) =
                    make_float2(sigmoidf(zp.x + d[i][j][0]),
                                sigmoidf(zp.y + d[i][j][1]));
            }
            if (R + 8 < n) {
                float2 zp = *(const float2*)(g_zp + (size_t)(R + 8) * 128 + C);
                *(float2*)(g_zp + (size_t)(R + 8) * 128 + C) =
                    make_float2(sigmoidf(zp.x + d[i][j][2]),
                                sigmoidf(zp.y + d[i][j][3]));
            }
        }
    }
    load_xA(sX, g_q, rowBase, n, tid);
    __syncthreads();

    ZERO_D(d);
    product(sX, &g_wimg[5 * 4096], d, wm, wn, lane);

    #pragma unroll
    for (int i = 0; i < 2; i++) {
        int R = rowBase + (wm * 2 + i) * 16 + (lane >> 2);
        #pragma unroll
        for (int j = 0; j < 8; j++) {
            int C = wn * 64 + j * 8 + (lane & 3) * 2;
            if (R < n) {
                float2 cp = *(const float2*)(g_cp + (size_t)R * 128 + C);
                float2 sv = *(const float2*)(g_s + (size_t)R * 128 + C);
                float2 zv = *(const float2*)(g_zp + (size_t)R * 128 + C);
                float t0 = tanh_fast(cp.x + d[i][j][0]);
                float t1 = tanh_fast(cp.y + d[i][j][1]);
                *(float2*)(out + (size_t)R * 128 + C) =
                    make_float2((1.f - zv.x) * sv.x + zv.x * t0,
                                (1.f - zv.y) * sv.y + zv.y * t1);
            }
            if (R + 8 < n) {
                float2 cp = *(const float2*)(g_cp + (size_t)(R + 8) * 128 + C);
                float2 sv = *(const float2*)(g_s + (size_t)(R + 8) * 128 + C);
                float2 zv = *(const float2*)(g_zp + (size_t)(R + 8) * 128 + C);
                float t0 = tanh_fast(cp.x + d[i][j][2]);
                float t1 = tanh_fast(cp.y + d[i][j][3]);
                *(float2*)(out + (size_t)(R + 8) * 128 + C) =
                    make_float2((1.f - zv.x) * sv.x + zv.x * t0,
                                (1.f - zv.y) * sv.y + zv.y * t1);
            }
        }
    }
}

// ---------------- launch ----------------
extern "C" void kernel_launch(void* const* d_in, const int* in_sizes, int n_in,
                              void* d_out, int out_size)
{
    const float* h    = (const float*)d_in[0];
    const float* fsrc = (const float*)d_in[1];
    const float* fdst = (const float*)d_in[2];
    const int*   src  = (const int*)d_in[3];
    const int*   dst  = (const int*)d_in[4];
    const float* wz   = (const float*)d_in[5];
    const float* uz   = (const float*)d_in[6];
    const float* bz   = (const float*)d_in[7];
    const float* wr   = (const float*)d_in[8];
    const float* ur   = (const float*)d_in[9];
    const float* br   = (const float*)d_in[10];
    const float* w    = (const float*)d_in[11];
    const float* u    = (const float*)d_in[12];
    const float* b    = (const float*)d_in[13];
    float* out = (float*)d_out;

    int n = in_sizes[0] / 128;
    int e = in_sizes[3];
    if (n > NMAX || e > EMAX) return;

    cudaFuncSetAttribute(k_gemmA, cudaFuncAttributeMaxDynamicSharedMemorySize, SM_TOT);
    cudaFuncSetAttribute(k_gemmB, cudaFuncAttributeMaxDynamicSharedMemorySize, SM_TOT);
    cudaFuncSetAttribute(k_gemmC, cudaFuncAttributeMaxDynamicSharedMemorySize, SM_TOT);

    int gemmBlocks = (n + 127) / 128;
    int nb = (n + 1023) / 1024;

    k_prep<<<dim3(16, 6), 256>>>(wz, w, wr, ur, uz, u);
    k_zero<<<(n + 255) / 256, 256>>>(n);
    k_hist<<<(e + 255) / 256, 256>>>(dst, e);
    k_part<<<nb, 1024>>>(n);
    k_scanb<<<1, 128>>>(nb);
    k_add<<<(n + 1023) / 1024, 1024>>>(n, e);
    k_scatter<<<(e + 255) / 256, 256>>>(src, dst, e);
    k_gemmB<<<gemmBlocks, 256, SM_TOT>>>(fdst, h, br, n);
    k_gemmA<<<gemmBlocks, 256, SM_TOT>>>(fsrc, bz, b, n);
    k_reduce<<<(n + 7) / 8, 256>>>(h, n);
    k_gemmC<<<gemmBlocks, 256, SM_TOT>>>(out, n);
}

// round 8
// speedup vs baseline: 4.8778x; 1.2474x over previous
#include <cuda_runtime.h>
#include <cstdint>

#define NMAX 100000
#define EMAX 1600000

// ---------------- scratch ----------------
__device__ float g_p [NMAX * 128];
__device__ float g_s [NMAX * 128];
__device__ float g_q [NMAX * 128];
__device__ int   g_cnt[NMAX];
__device__ int   g_off[NMAX + 1];
__device__ int   g_cur[NMAX];
__device__ int   g_perm[EMAX];
__device__ int   g_bsum[128];
__device__ int   g_bpre[128];
__device__ uint4 g_wimg[6 * 4096];   // 6 weight images, 64KB each, B-fragment order

__device__ __forceinline__ float sigmoidf(float x) { return 1.0f / (1.0f + __expf(-x)); }
__device__ __forceinline__ float tanh_fast(float x) {
    return __fdividef(2.0f, 1.0f + __expf(-2.0f * x)) - 1.0f;
}
__device__ __forceinline__ uint32_t totf32(float f) {
    uint32_t r; asm("cvt.rna.tf32.f32 %0,%1;" : "=r"(r) : "f"(f)); return r;
}

// ---------------- mma.sync m16n8k8 tf32 ----------------
__device__ __forceinline__ void mma8(float* d, const uint32_t* a, uint32_t b0, uint32_t b1) {
    asm("mma.sync.aligned.m16n8k8.row.col.f32.tf32.tf32.f32 "
        "{%0,%1,%2,%3},{%4,%5,%6,%7},{%8,%9},{%0,%1,%2,%3};"
        : "+f"(d[0]), "+f"(d[1]), "+f"(d[2]), "+f"(d[3])
        : "r"(a[0]), "r"(a[1]), "r"(a[2]), "r"(a[3]), "r"(b0), "r"(b1));
}

// ---------------- CSR build ----------------
__global__ void k_zero(int n) {
    int i = blockIdx.x * blockDim.x + threadIdx.x;
    if (i < n) g_cnt[i] = 0;
}
__global__ void k_hist(const int* __restrict__ dst, int e) {
    int i = blockIdx.x * blockDim.x + threadIdx.x;
    if (i < e) atomicAdd(&g_cnt[dst[i]], 1);
}

__global__ void k_part(int n) {
    __shared__ int sm[1024];
    int b = blockIdx.x, t = threadIdx.x;
    int idx = b * 1024 + t;
    int v = (idx < n) ? g_cnt[idx] : 0;
    sm[t] = v;
    __syncthreads();
    #pragma unroll
    for (int off = 1; off < 1024; off <<= 1) {
        int x = (t >= off) ? sm[t - off] : 0;
        __syncthreads();
        sm[t] += x;
        __syncthreads();
    }
    if (idx < n) g_off[idx] = sm[t] - v;
    if (t == 1023) g_bsum[b] = sm[t];
}

__global__ void k_scanb(int nb) {
    __shared__ int sm[128];
    int t = threadIdx.x;
    int v = (t < nb) ? g_bsum[t] : 0;
    sm[t] = v;
    __syncthreads();
    #pragma unroll
    for (int off = 1; off < 128; off <<= 1) {
        int x = (t >= off) ? sm[t - off] : 0;
        __syncthreads();
        sm[t] += x;
        __syncthreads();
    }
    if (t < nb) g_bpre[t] = sm[t] - v;
}

__global__ void k_add(int n, int e) {
    int idx = blockIdx.x * blockDim.x + threadIdx.x;
    if (idx < n) {
        int o = g_off[idx] + g_bpre[idx >> 10];
        g_off[idx] = o;
        g_cur[idx] = o;
    }
    if (idx == 0) g_off[n] = e;
}

__global__ void k_scatter(const int* __restrict__ src, const int* __restrict__ dst, int e) {
    int i = blockIdx.x * blockDim.x + threadIdx.x;
    if (i < e) {
        int d = dst[i];
        int pos = atomicAdd(&g_cur[d], 1);
        g_perm[pos] = src[i];
    }
}

// ---------------- segment reduce: warp per node, 4-edge unroll ----------------
__global__ void k_reduce(const float* __restrict__ h, int n) {
    int gw = (blockIdx.x * blockDim.x + threadIdx.x) >> 5;
    int lane = threadIdx.x & 31;
    if (gw >= n) return;
    int i0 = g_off[gw], i1 = g_off[gw + 1];
    const float4* h4 = (const float4*)h;
    const float4* p4 = (const float4*)g_p;
    float4 sa = make_float4(0.f, 0.f, 0.f, 0.f);
    float4 qa = make_float4(0.f, 0.f, 0.f, 0.f);
    int i = i0;
    for (; i + 3 < i1; i += 4) {
        int u0 = g_perm[i], u1 = g_perm[i + 1], u2 = g_perm[i + 2], u3 = g_perm[i + 3];
        float4 a0 = h4[u0 * 32 + lane];
        float4 a1 = h4[u1 * 32 + lane];
        float4 a2 = h4[u2 * 32 + lane];
        float4 a3 = h4[u3 * 32 + lane];
        float4 b0 = p4[u0 * 32 + lane];
        float4 b1 = p4[u1 * 32 + lane];
        float4 b2 = p4[u2 * 32 + lane];
        float4 b3 = p4[u3 * 32 + lane];
        sa.x += (a0.x + a1.x) + (a2.x + a3.x);
        sa.y += (a0.y + a1.y) + (a2.y + a3.y);
        sa.z += (a0.z + a1.z) + (a2.z + a3.z);
        sa.w += (a0.w + a1.w) + (a2.w + a3.w);
        qa.x += (b0.x + b1.x) + (b2.x + b3.x);
        qa.y += (b0.y + b1.y) + (b2.y + b3.y);
        qa.z += (b0.z + b1.z) + (b2.z + b3.z);
        qa.w += (b0.w + b1.w) + (b2.w + b3.w);
    }
    for (; i < i1; i++) {
        int u0 = g_perm[i];
        float4 a0 = h4[u0 * 32 + lane];
        float4 b0 = p4[u0 * 32 + lane];
        sa.x += a0.x; sa.y += a0.y; sa.z += a0.z; sa.w += a0.w;
        qa.x += b0.x; qa.y += b0.y; qa.z += b0.z; qa.w += b0.w;
    }
    ((float4*)g_s)[gw * 32 + lane] = sa;
    ((float4*)g_q)[gw * 32 + lane] = qa;
}

// ---------------- weight fragment image prep ----------------
__global__ void k_prep(const float* w0, const float* w1, const float* w2,
                       const float* w3, const float* w4, const float* w5) {
    int mat = blockIdx.y;
    int t = blockIdx.x * 256 + threadIdx.x;
    if (t >= 4096) return;
    const float* srcs[6] = {w0, w1, w2, w3, w4, w5};
    const float* W = srcs[mat];
    int nt = t >> 8, kp = (t >> 5) & 7, lane = t & 31;
    int n = nt * 8 + (lane >> 2);
    int kb = kp * 16 + (lane & 3);
    uint4 v;
    v.x = totf32(W[(kb + 0)  * 128 + n]);
    v.y = totf32(W[(kb + 4)  * 128 + n]);
    v.z = totf32(W[(kb + 8)  * 128 + n]);
    v.w = totf32(W[(kb + 12) * 128 + n]);
    g_wimg[mat * 4096 + t] = v;
}

// ---------------- GEMM layouts ----------------
#define XP    132
#define SM_B  (128 * XP * 4)        // 67584 (gemmB, 256 thr, 2 blocks/SM)
#define SM_AC (2 * 128 * XP * 4)    // 135168 (gemmAC, 512 thr, 1 block/SM)

template<int NT>
__device__ __forceinline__ void load_xT(float* sX, const float* __restrict__ x,
                                        int rowBase, int n, int tid) {
    const float4* s4 = (const float4*)x;
    #pragma unroll 4
    for (int i = tid; i < 4096; i += NT) {
        int m = i >> 5, c4 = i & 31;
        float4 v = (rowBase + m < n) ? s4[(size_t)(rowBase + m) * 32 + c4]
                                     : make_float4(0.f, 0.f, 0.f, 0.f);
        uint4 o;
        o.x = totf32(v.x); o.y = totf32(v.y); o.z = totf32(v.z); o.w = totf32(v.w);
        *(uint4*)(&sX[m * XP + c4 * 4]) = o;
    }
}

// ---- 256-thread (8 warp, 2x(wn) x 4x(wm)) product: 64-col slab, d[2][8][4] ----
__device__ __forceinline__ void product8(const float* sX, const uint4* __restrict__ gW,
                                         float d[2][8][4], int wm, int wn, int lane) {
    int r0a = (wm * 2 + 0) * 16 + (lane >> 2);
    int r0b = (wm * 2 + 1) * 16 + (lane >> 2);
    int kl = lane & 3;
    for (int kp = 0; kp < 8; kp++) {
        uint32_t a[2][2][4];
        #pragma unroll
        for (int s = 0; s < 2; s++) {
            int k0 = (kp * 2 + s) * 8 + kl;
            a[0][s][0] = __float_as_uint(sX[r0a * XP + k0]);
            a[0][s][1] = __float_as_uint(sX[(r0a + 8) * XP + k0]);
            a[0][s][2] = __float_as_uint(sX[r0a * XP + k0 + 4]);
            a[0][s][3] = __float_as_uint(sX[(r0a + 8) * XP + k0 + 4]);
            a[1][s][0] = __float_as_uint(sX[r0b * XP + k0]);
            a[1][s][1] = __float_as_uint(sX[(r0b + 8) * XP + k0]);
            a[1][s][2] = __float_as_uint(sX[r0b * XP + k0 + 4]);
            a[1][s][3] = __float_as_uint(sX[(r0b + 8) * XP + k0 + 4]);
        }
        #pragma unroll
        for (int j = 0; j < 8; j++) {
            uint4 b = __ldg(&gW[((wn * 8 + j) * 8 + kp) * 32 + lane]);
            mma8(d[0][j], a[0][0], b.x, b.y);
            mma8(d[1][j], a[1][0], b.x, b.y);
            mma8(d[0][j], a[0][1], b.z, b.w);
            mma8(d[1][j], a[1][1], b.z, b.w);
        }
    }
}

// ---- 512-thread (16 warp, 4m x 4n) product: 32-col slab, d[2][4][4] ----
__device__ __forceinline__ void product4(const float* sX, const uint4* __restrict__ gW,
                                         float d[2][4][4], int wm, int wn, int lane) {
    int r0a = wm * 32 + 0  + (lane >> 2);
    int r0b = wm * 32 + 16 + (lane >> 2);
    int kl = lane & 3;
    for (int kp = 0; kp < 8; kp++) {
        uint32_t a[2][2][4];
        #pragma unroll
        for (int s = 0; s < 2; s++) {
            int k0 = (kp * 2 + s) * 8 + kl;
            a[0][s][0] = __float_as_uint(sX[r0a * XP + k0]);
            a[0][s][1] = __float_as_uint(sX[(r0a + 8) * XP + k0]);
            a[0][s][2] = __float_as_uint(sX[r0a * XP + k0 + 4]);
            a[0][s][3] = __float_as_uint(sX[(r0a + 8) * XP + k0 + 4]);
            a[1][s][0] = __float_as_uint(sX[r0b * XP + k0]);
            a[1][s][1] = __float_as_uint(sX[(r0b + 8) * XP + k0]);
            a[1][s][2] = __float_as_uint(sX[r0b * XP + k0 + 4]);
            a[1][s][3] = __float_as_uint(sX[(r0b + 8) * XP + k0 + 4]);
        }
        #pragma unroll
        for (int j = 0; j < 4; j++) {
            uint4 b = __ldg(&gW[((wn * 4 + j) * 8 + kp) * 32 + lane]);
            mma8(d[0][j], a[0][0], b.x, b.y);
            mma8(d[1][j], a[1][0], b.x, b.y);
            mma8(d[0][j], a[0][1], b.z, b.w);
            mma8(d[1][j], a[1][1], b.z, b.w);
        }
    }
}

// p = sigmoid(fdst@wr + h@ur + br) * h  (h read back from smem tile, tf32)
__global__ void __launch_bounds__(256, 2) k_gemmB(const float* __restrict__ fdst,
                                                  const float* __restrict__ h,
                                                  const float* __restrict__ br, int n) {
    extern __shared__ char sm[];
    float* sX = (float*)sm;
    int tid = threadIdx.x, w = tid >> 5, lane = tid & 31;
    int wm = w >> 1, wn = w & 1;
    int rowBase = blockIdx.x * 128;

    load_xT<256>(sX, fdst, rowBase, n, tid);
    __syncthreads();

    float d[2][8][4];
    #pragma unroll
    for (int i = 0; i < 2; i++)
        #pragma unroll
        for (int j = 0; j < 8; j++)
            #pragma unroll
            for (int q = 0; q < 4; q++) d[i][j][q] = 0.f;

    product8(sX, &g_wimg[2 * 4096], d, wm, wn, lane);
    __syncthreads();
    load_xT<256>(sX, h, rowBase, n, tid);
    __syncthreads();
    product8(sX, &g_wimg[3 * 4096], d, wm, wn, lane);

    #pragma unroll
    for (int i = 0; i < 2; i++) {
        int Rl = (wm * 2 + i) * 16 + (lane >> 2);
        int R = rowBase + Rl;
        #pragma unroll
        for (int j = 0; j < 8; j++) {
            int C = wn * 64 + j * 8 + (lane & 3) * 2;
            float b0 = br[C], b1 = br[C + 1];
            if (R < n) {
                float h0 = sX[Rl * XP + C], h1 = sX[Rl * XP + C + 1];
                *(float2*)(g_p + (size_t)R * 128 + C) =
                    make_float2(sigmoidf(d[i][j][0] + b0) * h0,
                                sigmoidf(d[i][j][1] + b1) * h1);
            }
            if (R + 8 < n) {
                float h0 = sX[(Rl + 8) * XP + C], h1 = sX[(Rl + 8) * XP + C + 1];
                *(float2*)(g_p + (size_t)(R + 8) * 128 + C) =
                    make_float2(sigmoidf(d[i][j][2] + b0) * h0,
                                sigmoidf(d[i][j][3] + b1) * h1);
            }
        }
    }
}

// fused: z = sigmoid(fsrc@wz + s@uz + bz); ht = tanh(fsrc@w + q@u + b);
//        out = (1-z)*s + z*ht
__global__ void __launch_bounds__(512, 1) k_gemmAC(const float* __restrict__ fsrc,
                                                   const float* __restrict__ bz,
                                                   const float* __restrict__ b,
                                                   float* __restrict__ out, int n) {
    extern __shared__ char sm[];
    float* sS = (float*)sm;                    // s tile (tf32 bits), persistent
    float* sX = (float*)(sm + 128 * XP * 4);   // q tile, then fsrc tile
    int tid = threadIdx.x, w = tid >> 5, lane = tid & 31;
    int wm = w >> 2, wn = w & 3;
    int rowBase = blockIdx.x * 128;

    load_xT<512>(sS, g_s, rowBase, n, tid);
    load_xT<512>(sX, g_q, rowBase, n, tid);
    __syncthreads();

    float d1[2][4][4], d2[2][4][4];
    #pragma unroll
    for (int i = 0; i < 2; i++)
        #pragma unroll
        for (int j = 0; j < 4; j++)
            #pragma unroll
            for (int q = 0; q < 4; q++) { d1[i][j][q] = 0.f; d2[i][j][q] = 0.f; }

    product4(sS, &g_wimg[4 * 4096], d1, wm, wn, lane);   // s @ uz
    product4(sX, &g_wimg[5 * 4096], d2, wm, wn, lane);   // q @ u
    __syncthreads();
    load_xT<512>(sX, fsrc, rowBase, n, tid);
    __syncthreads();
    product4(sX, &g_wimg[0 * 4096], d1, wm, wn, lane);   // + fsrc @ wz
    product4(sX, &g_wimg[1 * 4096], d2, wm, wn, lane);   // + fsrc @ w

    #pragma unroll
    for (int i = 0; i < 2; i++) {
        int Rl = wm * 32 + i * 16 + (lane >> 2);
        int R = rowBase + Rl;
        #pragma unroll
        for (int j = 0; j < 4; j++) {
            int C = wn * 32 + j * 8 + (lane & 3) * 2;
            float bz0 = bz[C], bz1 = bz[C + 1];
            float bb0 = b[C],  bb1 = b[C + 1];
            if (R < n) {
                float s0 = sS[Rl * XP + C], s1 = sS[Rl * XP + C + 1];
                float z0 = sigmoidf(d1[i][j][0] + bz0);
                float z1 = sigmoidf(d1[i][j][1] + bz1);
                float t0 = tanh_fast(d2[i][j][0] + bb0);
                float t1 = tanh_fast(d2[i][j][1] + bb1);
                *(float2*)(out + (size_t)R * 128 + C) =
                    make_float2((1.f - z0) * s0 + z0 * t0,
                                (1.f - z1) * s1 + z1 * t1);
            }
            if (R + 8 < n) {
                float s0 = sS[(Rl + 8) * XP + C], s1 = sS[(Rl + 8) * XP + C + 1];
                float z0 = sigmoidf(d1[i][j][2] + bz0);
                float z1 = sigmoidf(d1[i][j][3] + bz1);
                float t0 = tanh_fast(d2[i][j][2] + bb0);
                float t1 = tanh_fast(d2[i][j][3] + bb1);
                *(float2*)(out + (size_t)(R + 8) * 128 + C) =
                    make_float2((1.f - z0) * s0 + z0 * t0,
                                (1.f - z1) * s1 + z1 * t1);
            }
        }
    }
}

// ---------------- launch ----------------
extern "C" void kernel_launch(void* const* d_in, const int* in_sizes, int n_in,
                              void* d_out, int out_size)
{
    const float* h    = (const float*)d_in[0];
    const float* fsrc = (const float*)d_in[1];
    const float* fdst = (const float*)d_in[2];
    const int*   src  = (const int*)d_in[3];
    const int*   dst  = (const int*)d_in[4];
    const float* wz   = (const float*)d_in[5];
    const float* uz   = (const float*)d_in[6];
    const float* bz   = (const float*)d_in[7];
    const float* wr   = (const float*)d_in[8];
    const float* ur   = (const float*)d_in[9];
    const float* br   = (const float*)d_in[10];
    const float* w    = (const float*)d_in[11];
    const float* u    = (const float*)d_in[12];
    const float* b    = (const float*)d_in[13];
    float* out = (float*)d_out;

    int n = in_sizes[0] / 128;
    int e = in_sizes[3];
    if (n > NMAX || e > EMAX) return;

    cudaFuncSetAttribute(k_gemmB,  cudaFuncAttributeMaxDynamicSharedMemorySize, SM_B);
    cudaFuncSetAttribute(k_gemmAC, cudaFuncAttributeMaxDynamicSharedMemorySize, SM_AC);

    int gemmBlocks = (n + 127) / 128;
    int nb = (n + 1023) / 1024;

    k_prep<<<dim3(16, 6), 256>>>(wz, w, wr, ur, uz, u);
    k_zero<<<(n + 255) / 256, 256>>>(n);
    k_hist<<<(e + 255) / 256, 256>>>(dst, e);
    k_part<<<nb, 1024>>>(n);
    k_scanb<<<1, 128>>>(nb);
    k_add<<<(n + 1023) / 1024, 1024>>>(n, e);
    k_scatter<<<(e + 255) / 256, 256>>>(src, dst, e);
    k_gemmB<<<gemmBlocks, 256, SM_B>>>(fdst, h, br, n);
    k_reduce<<<(n + 7) / 8, 256>>>(h, n);
    k_gemmAC<<<gemmBlocks, 512, SM_AC>>>(fsrc, bz, b, out, n);
}

// round 9
// speedup vs baseline: 5.1955x; 1.0651x over previous
#include <cuda_runtime.h>
#include <cuda_bf16.h>
#include <cstdint>

#define NMAX 100000
#define EMAX 1600000

// ---------------- scratch ----------------
__device__ __nv_bfloat162 g_pb[NMAX * 64];   // p compressed to bf16 (gather operand)
__device__ float g_s [NMAX * 128];
__device__ float g_q [NMAX * 128];
__device__ int   g_cnt[NMAX];
__device__ int   g_off[NMAX + 1];
__device__ int   g_cur[NMAX];
__device__ int   g_perm[EMAX];
__device__ int   g_bsum[128];
__device__ int   g_bpre[128];
__device__ uint4 g_wimg[6 * 4096];   // 6 weight images, 64KB each, B-fragment order

__device__ __forceinline__ float sigmoidf(float x) { return 1.0f / (1.0f + __expf(-x)); }
__device__ __forceinline__ float tanh_fast(float x) {
    return __fdividef(2.0f, 1.0f + __expf(-2.0f * x)) - 1.0f;
}
__device__ __forceinline__ uint32_t totf32(float f) {
    uint32_t r; asm("cvt.rna.tf32.f32 %0,%1;" : "=r"(r) : "f"(f)); return r;
}

// ---------------- mma.sync m16n8k8 tf32 ----------------
__device__ __forceinline__ void mma8(float* d, const uint32_t* a, uint32_t b0, uint32_t b1) {
    asm("mma.sync.aligned.m16n8k8.row.col.f32.tf32.tf32.f32 "
        "{%0,%1,%2,%3},{%4,%5,%6,%7},{%8,%9},{%0,%1,%2,%3};"
        : "+f"(d[0]), "+f"(d[1]), "+f"(d[2]), "+f"(d[3])
        : "r"(a[0]), "r"(a[1]), "r"(a[2]), "r"(a[3]), "r"(b0), "r"(b1));
}

// ---------------- CSR build ----------------
__global__ void k_zero(int n) {
    int i = blockIdx.x * blockDim.x + threadIdx.x;
    if (i < n) g_cnt[i] = 0;
}
__global__ void k_hist(const int* __restrict__ dst, int e) {
    int i = blockIdx.x * blockDim.x + threadIdx.x;
    if (i < e) atomicAdd(&g_cnt[dst[i]], 1);
}

__global__ void k_part(int n) {
    __shared__ int sm[1024];
    int b = blockIdx.x, t = threadIdx.x;
    int idx = b * 1024 + t;
    int v = (idx < n) ? g_cnt[idx] : 0;
    sm[t] = v;
    __syncthreads();
    #pragma unroll
    for (int off = 1; off < 1024; off <<= 1) {
        int x = (t >= off) ? sm[t - off] : 0;
        __syncthreads();
        sm[t] += x;
        __syncthreads();
    }
    if (idx < n) g_off[idx] = sm[t] - v;
    if (t == 1023) g_bsum[b] = sm[t];
}

__global__ void k_scanb(int nb) {
    __shared__ int sm[128];
    int t = threadIdx.x;
    int v = (t < nb) ? g_bsum[t] : 0;
    sm[t] = v;
    __syncthreads();
    #pragma unroll
    for (int off = 1; off < 128; off <<= 1) {
        int x = (t >= off) ? sm[t - off] : 0;
        __syncthreads();
        sm[t] += x;
        __syncthreads();
    }
    if (t < nb) g_bpre[t] = sm[t] - v;
}

__global__ void k_add(int n, int e) {
    int idx = blockIdx.x * blockDim.x + threadIdx.x;
    if (idx < n) {
        int o = g_off[idx] + g_bpre[idx >> 10];
        g_off[idx] = o;
        g_cur[idx] = o;
    }
    if (idx == 0) g_off[n] = e;
}

__global__ void k_scatter(const int* __restrict__ src, const int* __restrict__ dst, int e) {
    int i = blockIdx.x * blockDim.x + threadIdx.x;
    if (i < e) {
        int d = dst[i];
        int pos = atomicAdd(&g_cur[d], 1);
        g_perm[pos] = src[i];
    }
}

// ---------------- segment reduce: warp per node; h fp32, p bf16 ----------------
__global__ void k_reduce(const float* __restrict__ h, int n) {
    int gw = (blockIdx.x * blockDim.x + threadIdx.x) >> 5;
    int lane = threadIdx.x & 31;
    if (gw >= n) return;
    int i0 = g_off[gw], i1 = g_off[gw + 1];
    const float4* h4 = (const float4*)h;
    const uint2* pb = (const uint2*)g_pb;   // 32 uint2 per row; lane -> cols 4l..4l+3
    float4 sa = make_float4(0.f, 0.f, 0.f, 0.f);
    float4 qa = make_float4(0.f, 0.f, 0.f, 0.f);
    int i = i0;
    for (; i + 3 < i1; i += 4) {
        int u0 = g_perm[i], u1 = g_perm[i + 1], u2 = g_perm[i + 2], u3 = g_perm[i + 3];
        float4 a0 = h4[u0 * 32 + lane];
        float4 a1 = h4[u1 * 32 + lane];
        float4 a2 = h4[u2 * 32 + lane];
        float4 a3 = h4[u3 * 32 + lane];
        uint2 b0 = pb[u0 * 32 + lane];
        uint2 b1 = pb[u1 * 32 + lane];
        uint2 b2 = pb[u2 * 32 + lane];
        uint2 b3 = pb[u3 * 32 + lane];
        sa.x += (a0.x + a1.x) + (a2.x + a3.x);
        sa.y += (a0.y + a1.y) + (a2.y + a3.y);
        sa.z += (a0.z + a1.z) + (a2.z + a3.z);
        sa.w += (a0.w + a1.w) + (a2.w + a3.w);
        float2 f0 = __bfloat1622float2(*(__nv_bfloat162*)&b0.x);
        float2 g0 = __bfloat1622float2(*(__nv_bfloat162*)&b0.y);
        float2 f1 = __bfloat1622float2(*(__nv_bfloat162*)&b1.x);
        float2 g1 = __bfloat1622float2(*(__nv_bfloat162*)&b1.y);
        float2 f2 = __bfloat1622float2(*(__nv_bfloat162*)&b2.x);
        float2 g2 = __bfloat1622float2(*(__nv_bfloat162*)&b2.y);
        float2 f3 = __bfloat1622float2(*(__nv_bfloat162*)&b3.x);
        float2 g3 = __bfloat1622float2(*(__nv_bfloat162*)&b3.y);
        qa.x += (f0.x + f1.x) + (f2.x + f3.x);
        qa.y += (f0.y + f1.y) + (f2.y + f3.y);
        qa.z += (g0.x + g1.x) + (g2.x + g3.x);
        qa.w += (g0.y + g1.y) + (g2.y + g3.y);
    }
    for (; i < i1; i++) {
        int u0 = g_perm[i];
        float4 a0 = h4[u0 * 32 + lane];
        uint2 b0 = pb[u0 * 32 + lane];
        float2 f0 = __bfloat1622float2(*(__nv_bfloat162*)&b0.x);
        float2 g0 = __bfloat1622float2(*(__nv_bfloat162*)&b0.y);
        sa.x += a0.x; sa.y += a0.y; sa.z += a0.z; sa.w += a0.w;
        qa.x += f0.x; qa.y += f0.y; qa.z += g0.x; qa.w += g0.y;
    }
    ((float4*)g_s)[gw * 32 + lane] = sa;
    ((float4*)g_q)[gw * 32 + lane] = qa;
}

// ---------------- weight fragment image prep ----------------
__global__ void k_prep(const float* w0, const float* w1, const float* w2,
                       const float* w3, const float* w4, const float* w5) {
    int mat = blockIdx.y;
    int t = blockIdx.x * 256 + threadIdx.x;
    if (t >= 4096) return;
    const float* srcs[6] = {w0, w1, w2, w3, w4, w5};
    const float* W = srcs[mat];
    int nt = t >> 8, kp = (t >> 5) & 7, lane = t & 31;
    int n = nt * 8 + (lane >> 2);
    int kb = kp * 16 + (lane & 3);
    uint4 v;
    v.x = totf32(W[(kb + 0)  * 128 + n]);
    v.y = totf32(W[(kb + 4)  * 128 + n]);
    v.z = totf32(W[(kb + 8)  * 128 + n]);
    v.w = totf32(W[(kb + 12) * 128 + n]);
    g_wimg[mat * 4096 + t] = v;
}

// ---------------- GEMM layouts ----------------
#define XP    132
#define SM_B  (128 * XP * 4)        // 67584 (gemmB, 256 thr, 2 blocks/SM)
#define SM_AC (2 * 128 * XP * 4)    // 135168 (gemmAC, 512 thr, 1 block/SM)

template<int NT>
__device__ __forceinline__ void load_xT(float* sX, const float* __restrict__ x,
                                        int rowBase, int n, int tid) {
    const float4* s4 = (const float4*)x;
    #pragma unroll 4
    for (int i = tid; i < 4096; i += NT) {
        int m = i >> 5, c4 = i & 31;
        float4 v = (rowBase + m < n) ? s4[(size_t)(rowBase + m) * 32 + c4]
                                     : make_float4(0.f, 0.f, 0.f, 0.f);
        uint4 o;
        o.x = totf32(v.x); o.y = totf32(v.y); o.z = totf32(v.z); o.w = totf32(v.w);
        *(uint4*)(&sX[m * XP + c4 * 4]) = o;
    }
}

// ---- 256-thread (8 warp, 2(wn) x 4(wm)) product: 64-col slab, d[2][8][4] ----
__device__ __forceinline__ void product8(const float* sX, const uint4* __restrict__ gW,
                                         float d[2][8][4], int wm, int wn, int lane) {
    int r0a = (wm * 2 + 0) * 16 + (lane >> 2);
    int r0b = (wm * 2 + 1) * 16 + (lane >> 2);
    int kl = lane & 3;
    for (int kp = 0; kp < 8; kp++) {
        uint32_t a[2][2][4];
        #pragma unroll
        for (int s = 0; s < 2; s++) {
            int k0 = (kp * 2 + s) * 8 + kl;
            a[0][s][0] = __float_as_uint(sX[r0a * XP + k0]);
            a[0][s][1] = __float_as_uint(sX[(r0a + 8) * XP + k0]);
            a[0][s][2] = __float_as_uint(sX[r0a * XP + k0 + 4]);
            a[0][s][3] = __float_as_uint(sX[(r0a + 8) * XP + k0 + 4]);
            a[1][s][0] = __float_as_uint(sX[r0b * XP + k0]);
            a[1][s][1] = __float_as_uint(sX[(r0b + 8) * XP + k0]);
            a[1][s][2] = __float_as_uint(sX[r0b * XP + k0 + 4]);
            a[1][s][3] = __float_as_uint(sX[(r0b + 8) * XP + k0 + 4]);
        }
        #pragma unroll
        for (int j = 0; j < 8; j++) {
            uint4 b = __ldg(&gW[((wn * 8 + j) * 8 + kp) * 32 + lane]);
            mma8(d[0][j], a[0][0], b.x, b.y);
            mma8(d[1][j], a[1][0], b.x, b.y);
            mma8(d[0][j], a[0][1], b.z, b.w);
            mma8(d[1][j], a[1][1], b.z, b.w);
        }
    }
}

// ---- 512-thread (16 warp, 4m x 4n) product: 32-col slab, d[2][4][4] ----
__device__ __forceinline__ void product4(const float* sX, const uint4* __restrict__ gW,
                                         float d[2][4][4], int wm, int wn, int lane) {
    int r0a = wm * 32 + 0  + (lane >> 2);
    int r0b = wm * 32 + 16 + (lane >> 2);
    int kl = lane & 3;
    for (int kp = 0; kp < 8; kp++) {
        uint32_t a[2][2][4];
        #pragma unroll
        for (int s = 0; s < 2; s++) {
            int k0 = (kp * 2 + s) * 8 + kl;
            a[0][s][0] = __float_as_uint(sX[r0a * XP + k0]);
            a[0][s][1] = __float_as_uint(sX[(r0a + 8) * XP + k0]);
            a[0][s][2] = __float_as_uint(sX[r0a * XP + k0 + 4]);
            a[0][s][3] = __float_as_uint(sX[(r0a + 8) * XP + k0 + 4]);
            a[1][s][0] = __float_as_uint(sX[r0b * XP + k0]);
            a[1][s][1] = __float_as_uint(sX[(r0b + 8) * XP + k0]);
            a[1][s][2] = __float_as_uint(sX[r0b * XP + k0 + 4]);
            a[1][s][3] = __float_as_uint(sX[(r0b + 8) * XP + k0 + 4]);
        }
        #pragma unroll
        for (int j = 0; j < 4; j++) {
            uint4 b = __ldg(&gW[((wn * 4 + j) * 8 + kp) * 32 + lane]);
            mma8(d[0][j], a[0][0], b.x, b.y);
            mma8(d[1][j], a[1][0], b.x, b.y);
            mma8(d[0][j], a[0][1], b.z, b.w);
            mma8(d[1][j], a[1][1], b.z, b.w);
        }
    }
}

// p = sigmoid(fdst@wr + h@ur + br) * h  -> bf16 g_pb
__global__ void __launch_bounds__(256, 2) k_gemmB(const float* __restrict__ fdst,
                                                  const float* __restrict__ h,
                                                  const float* __restrict__ br, int n) {
    extern __shared__ char sm[];
    float* sX = (float*)sm;
    int tid = threadIdx.x, w = tid >> 5, lane = tid & 31;
    int wm = w >> 1, wn = w & 1;
    int rowBase = blockIdx.x * 128;

    load_xT<256>(sX, fdst, rowBase, n, tid);
    __syncthreads();

    float d[2][8][4];
    #pragma unroll
    for (int i = 0; i < 2; i++)
        #pragma unroll
        for (int j = 0; j < 8; j++)
            #pragma unroll
            for (int q = 0; q < 4; q++) d[i][j][q] = 0.f;

    product8(sX, &g_wimg[2 * 4096], d, wm, wn, lane);
    __syncthreads();
    load_xT<256>(sX, h, rowBase, n, tid);
    __syncthreads();
    product8(sX, &g_wimg[3 * 4096], d, wm, wn, lane);

    #pragma unroll
    for (int i = 0; i < 2; i++) {
        int Rl = (wm * 2 + i) * 16 + (lane >> 2);
        int R = rowBase + Rl;
        #pragma unroll
        for (int j = 0; j < 8; j++) {
            int C = wn * 64 + j * 8 + (lane & 3) * 2;
            float b0 = br[C], b1 = br[C + 1];
            if (R < n) {
                float h0 = sX[Rl * XP + C], h1 = sX[Rl * XP + C + 1];
                g_pb[(size_t)R * 64 + (C >> 1)] =
                    __floats2bfloat162_rn(sigmoidf(d[i][j][0] + b0) * h0,
                                          sigmoidf(d[i][j][1] + b1) * h1);
            }
            if (R + 8 < n) {
                float h0 = sX[(Rl + 8) * XP + C], h1 = sX[(Rl + 8) * XP + C + 1];
                g_pb[(size_t)(R + 8) * 64 + (C >> 1)] =
                    __floats2bfloat162_rn(sigmoidf(d[i][j][2] + b0) * h0,
                                          sigmoidf(d[i][j][3] + b1) * h1);
            }
        }
    }
}

// fused: z = sigmoid(fsrc@wz + s@uz + bz); ht = tanh(fsrc@w + q@u + b);
//        out = (1-z)*s + z*ht
__global__ void __launch_bounds__(512, 1) k_gemmAC(const float* __restrict__ fsrc,
                                                   const float* __restrict__ bz,
                                                   const float* __restrict__ b,
                                                   float* __restrict__ out, int n) {
    extern __shared__ char sm[];
    float* sS = (float*)sm;                    // s tile (tf32 bits), persistent
    float* sX = (float*)(sm + 128 * XP * 4);   // q tile, then fsrc tile
    int tid = threadIdx.x, w = tid >> 5, lane = tid & 31;
    int wm = w >> 2, wn = w & 3;
    int rowBase = blockIdx.x * 128;

    load_xT<512>(sS, g_s, rowBase, n, tid);
    load_xT<512>(sX, g_q, rowBase, n, tid);
    __syncthreads();

    float d1[2][4][4], d2[2][4][4];
    #pragma unroll
    for (int i = 0; i < 2; i++)
        #pragma unroll
        for (int j = 0; j < 4; j++)
            #pragma unroll
            for (int q = 0; q < 4; q++) { d1[i][j][q] = 0.f; d2[i][j][q] = 0.f; }

    product4(sS, &g_wimg[4 * 4096], d1, wm, wn, lane);   // s @ uz
    product4(sX, &g_wimg[5 * 4096], d2, wm, wn, lane);   // q @ u
    __syncthreads();
    load_xT<512>(sX, fsrc, rowBase, n, tid);
    __syncthreads();
    product4(sX, &g_wimg[0 * 4096], d1, wm, wn, lane);   // + fsrc @ wz
    product4(sX, &g_wimg[1 * 4096], d2, wm, wn, lane);   // + fsrc @ w

    #pragma unroll
    for (int i = 0; i < 2; i++) {
        int Rl = wm * 32 + i * 16 + (lane >> 2);
        int R = rowBase + Rl;
        #pragma unroll
        for (int j = 0; j < 4; j++) {
            int C = wn * 32 + j * 8 + (lane & 3) * 2;
            float bz0 = bz[C], bz1 = bz[C + 1];
            float bb0 = b[C],  bb1 = b[C + 1];
            if (R < n) {
                float s0 = sS[Rl * XP + C], s1 = sS[Rl * XP + C + 1];
                float z0 = sigmoidf(d1[i][j][0] + bz0);
                float z1 = sigmoidf(d1[i][j][1] + bz1);
                float t0 = tanh_fast(d2[i][j][0] + bb0);
                float t1 = tanh_fast(d2[i][j][1] + bb1);
                *(float2*)(out + (size_t)R * 128 + C) =
                    make_float2((1.f - z0) * s0 + z0 * t0,
                                (1.f - z1) * s1 + z1 * t1);
            }
            if (R + 8 < n) {
                float s0 = sS[(Rl + 8) * XP + C], s1 = sS[(Rl + 8) * XP + C + 1];
                float z0 = sigmoidf(d1[i][j][2] + bz0);
                float z1 = sigmoidf(d1[i][j][3] + bz1);
                float t0 = tanh_fast(d2[i][j][2] + bb0);
                float t1 = tanh_fast(d2[i][j][3] + bb1);
                *(float2*)(out + (size_t)(R + 8) * 128 + C) =
                    make_float2((1.f - z0) * s0 + z0 * t0,
                                (1.f - z1) * s1 + z1 * t1);
            }
        }
    }
}

// ---------------- launch ----------------
extern "C" void kernel_launch(void* const* d_in, const int* in_sizes, int n_in,
                              void* d_out, int out_size)
{
    const float* h    = (const float*)d_in[0];
    const float* fsrc = (const float*)d_in[1];
    const float* fdst = (const float*)d_in[2];
    const int*   src  = (const int*)d_in[3];
    const int*   dst  = (const int*)d_in[4];
    const float* wz   = (const float*)d_in[5];
    const float* uz   = (const float*)d_in[6];
    const float* bz   = (const float*)d_in[7];
    const float* wr   = (const float*)d_in[8];
    const float* ur   = (const float*)d_in[9];
    const float* br   = (const float*)d_in[10];
    const float* w    = (const float*)d_in[11];
    const float* u    = (const float*)d_in[12];
    const float* b    = (const float*)d_in[13];
    float* out = (float*)d_out;

    int n = in_sizes[0] / 128;
    int e = in_sizes[3];
    if (n > NMAX || e > EMAX) return;

    static cudaStream_t sB = nullptr;
    static cudaEvent_t evF = nullptr, evJ = nullptr;
    if (!sB) {
        cudaStreamCreateWithFlags(&sB, cudaStreamNonBlocking);
        cudaEventCreateWithFlags(&evF, cudaEventDisableTiming);
        cudaEventCreateWithFlags(&evJ, cudaEventDisableTiming);
    }

    cudaFuncSetAttribute(k_gemmB,  cudaFuncAttributeMaxDynamicSharedMemorySize, SM_B);
    cudaFuncSetAttribute(k_gemmAC, cudaFuncAttributeMaxDynamicSharedMemorySize, SM_AC);

    int gemmBlocks = (n + 127) / 128;
    int nb = (n + 1023) / 1024;

    // fork: branch B (prep + gemmB) runs concurrently with the CSR chain
    cudaEventRecord(evF, 0);
    cudaStreamWaitEvent(sB, evF, 0);
    k_prep<<<dim3(16, 6), 256, 0, sB>>>(wz, w, wr, ur, uz, u);
    k_gemmB<<<gemmBlocks, 256, SM_B, sB>>>(fdst, h, br, n);
    cudaEventRecord(evJ, sB);

    // branch A: CSR chain on main stream
    k_zero<<<(n + 255) / 256, 256>>>(n);
    k_hist<<<(e + 255) / 256, 256>>>(dst, e);
    k_part<<<nb, 1024>>>(n);
    k_scanb<<<1, 128>>>(nb);
    k_add<<<(n + 1023) / 1024, 1024>>>(n, e);
    k_scatter<<<(e + 255) / 256, 256>>>(src, dst, e);

    // join, then reduce + fused gate GEMM
    cudaStreamWaitEvent(0, evJ, 0);
    k_reduce<<<(n + 7) / 8, 256>>>(h, n);
    k_gemmAC<<<gemmBlocks, 512, SM_AC>>>(fsrc, bz, b, out, n);
}

// round 10
// speedup vs baseline: 5.6286x; 1.0834x over previous
#include <cuda_runtime.h>
#include <cuda_bf16.h>
#include <cstdint>

#define NMAX 100000
#define EMAX 1600000

// ---------------- scratch ----------------
__device__ __nv_bfloat162 g_pb[NMAX * 64];   // p compressed to bf16 (gather operand)
__device__ float g_s [NMAX * 128];
__device__ float g_q [NMAX * 128];
__device__ int   g_cnt[NMAX];
__device__ int   g_off[NMAX + 1];
__device__ int   g_cur[NMAX];
__device__ int   g_perm[EMAX];
__device__ int   g_bsum[128];
__device__ int   g_bpre[128];
__device__ uint4 g_wimg[6 * 4096];   // 6 weight images, 64KB each, B-fragment order

__device__ __forceinline__ float sigmoidf(float x) { return 1.0f / (1.0f + __expf(-x)); }
__device__ __forceinline__ float tanh_fast(float x) {
    return __fdividef(2.0f, 1.0f + __expf(-2.0f * x)) - 1.0f;
}
__device__ __forceinline__ uint32_t totf32(float f) {
    uint32_t r; asm("cvt.rna.tf32.f32 %0,%1;" : "=r"(r) : "f"(f)); return r;
}

// ---------------- mma.sync m16n8k8 tf32 ----------------
__device__ __forceinline__ void mma8(float* d, const uint32_t* a, uint32_t b0, uint32_t b1) {
    asm("mma.sync.aligned.m16n8k8.row.col.f32.tf32.tf32.f32 "
        "{%0,%1,%2,%3},{%4,%5,%6,%7},{%8,%9},{%0,%1,%2,%3};"
        : "+f"(d[0]), "+f"(d[1]), "+f"(d[2]), "+f"(d[3])
        : "r"(a[0]), "r"(a[1]), "r"(a[2]), "r"(a[3]), "r"(b0), "r"(b1));
}

// ---------------- CSR build ----------------
__global__ void k_zero(int n) {
    int i = blockIdx.x * blockDim.x + threadIdx.x;
    if (i < n) g_cnt[i] = 0;
}
__global__ void k_hist(const int* __restrict__ dst, int e) {
    int i = blockIdx.x * blockDim.x + threadIdx.x;
    if (i < e) atomicAdd(&g_cnt[dst[i]], 1);
}

__global__ void k_part(int n) {
    __shared__ int sm[1024];
    int b = blockIdx.x, t = threadIdx.x;
    int idx = b * 1024 + t;
    int v = (idx < n) ? g_cnt[idx] : 0;
    sm[t] = v;
    __syncthreads();
    #pragma unroll
    for (int off = 1; off < 1024; off <<= 1) {
        int x = (t >= off) ? sm[t - off] : 0;
        __syncthreads();
        sm[t] += x;
        __syncthreads();
    }
    if (idx < n) g_off[idx] = sm[t] - v;
    if (t == 1023) g_bsum[b] = sm[t];
}

__global__ void k_scanb(int nb) {
    __shared__ int sm[128];
    int t = threadIdx.x;
    int v = (t < nb) ? g_bsum[t] : 0;
    sm[t] = v;
    __syncthreads();
    #pragma unroll
    for (int off = 1; off < 128; off <<= 1) {
        int x = (t >= off) ? sm[t - off] : 0;
        __syncthreads();
        sm[t] += x;
        __syncthreads();
    }
    if (t < nb) g_bpre[t] = sm[t] - v;
}

__global__ void k_add(int n, int e) {
    int idx = blockIdx.x * blockDim.x + threadIdx.x;
    if (idx < n) {
        int o = g_off[idx] + g_bpre[idx >> 10];
        g_off[idx] = o;
        g_cur[idx] = o;
    }
    if (idx == 0) g_off[n] = e;
}

__global__ void k_scatter(const int* __restrict__ src, const int* __restrict__ dst, int e) {
    int i = blockIdx.x * blockDim.x + threadIdx.x;
    if (i < e) {
        int d = dst[i];
        int pos = atomicAdd(&g_cur[d], 1);
        g_perm[pos] = src[i];
    }
}

// ---------------- segment reduce, split: s (fp32 h) / q (bf16 p) ----------------
__global__ void k_reduceS(const float* __restrict__ h, int n) {
    int gw = (blockIdx.x * blockDim.x + threadIdx.x) >> 5;
    int lane = threadIdx.x & 31;
    if (gw >= n) return;
    int i0 = g_off[gw], i1 = g_off[gw + 1];
    const float4* h4 = (const float4*)h;
    float4 sa = make_float4(0.f, 0.f, 0.f, 0.f);
    int i = i0;
    for (; i + 3 < i1; i += 4) {
        int u0 = g_perm[i], u1 = g_perm[i + 1], u2 = g_perm[i + 2], u3 = g_perm[i + 3];
        float4 a0 = h4[u0 * 32 + lane];
        float4 a1 = h4[u1 * 32 + lane];
        float4 a2 = h4[u2 * 32 + lane];
        float4 a3 = h4[u3 * 32 + lane];
        sa.x += (a0.x + a1.x) + (a2.x + a3.x);
        sa.y += (a0.y + a1.y) + (a2.y + a3.y);
        sa.z += (a0.z + a1.z) + (a2.z + a3.z);
        sa.w += (a0.w + a1.w) + (a2.w + a3.w);
    }
    for (; i < i1; i++) {
        int u0 = g_perm[i];
        float4 a0 = h4[u0 * 32 + lane];
        sa.x += a0.x; sa.y += a0.y; sa.z += a0.z; sa.w += a0.w;
    }
    ((float4*)g_s)[gw * 32 + lane] = sa;
}

__global__ void k_reduceQ(int n) {
    int gw = (blockIdx.x * blockDim.x + threadIdx.x) >> 5;
    int lane = threadIdx.x & 31;
    if (gw >= n) return;
    int i0 = g_off[gw], i1 = g_off[gw + 1];
    const uint2* pb = (const uint2*)g_pb;   // lane -> cols 4l..4l+3
    float4 qa = make_float4(0.f, 0.f, 0.f, 0.f);
    int i = i0;
    for (; i + 3 < i1; i += 4) {
        int u0 = g_perm[i], u1 = g_perm[i + 1], u2 = g_perm[i + 2], u3 = g_perm[i + 3];
        uint2 b0 = pb[u0 * 32 + lane];
        uint2 b1 = pb[u1 * 32 + lane];
        uint2 b2 = pb[u2 * 32 + lane];
        uint2 b3 = pb[u3 * 32 + lane];
        float2 f0 = __bfloat1622float2(*(__nv_bfloat162*)&b0.x);
        float2 g0 = __bfloat1622float2(*(__nv_bfloat162*)&b0.y);
        float2 f1 = __bfloat1622float2(*(__nv_bfloat162*)&b1.x);
        float2 g1 = __bfloat1622float2(*(__nv_bfloat162*)&b1.y);
        float2 f2 = __bfloat1622float2(*(__nv_bfloat162*)&b2.x);
        float2 g2 = __bfloat1622float2(*(__nv_bfloat162*)&b2.y);
        float2 f3 = __bfloat1622float2(*(__nv_bfloat162*)&b3.x);
        float2 g3 = __bfloat1622float2(*(__nv_bfloat162*)&b3.y);
        qa.x += (f0.x + f1.x) + (f2.x + f3.x);
        qa.y += (f0.y + f1.y) + (f2.y + f3.y);
        qa.z += (g0.x + g1.x) + (g2.x + g3.x);
        qa.w += (g0.y + g1.y) + (g2.y + g3.y);
    }
    for (; i < i1; i++) {
        int u0 = g_perm[i];
        uint2 b0 = pb[u0 * 32 + lane];
        float2 f0 = __bfloat1622float2(*(__nv_bfloat162*)&b0.x);
        float2 g0 = __bfloat1622float2(*(__nv_bfloat162*)&b0.y);
        qa.x += f0.x; qa.y += f0.y; qa.z += g0.x; qa.w += g0.y;
    }
    ((float4*)g_q)[gw * 32 + lane] = qa;
}

// ---------------- weight fragment image prep ----------------
__global__ void k_prep(const float* w0, const float* w1, const float* w2,
                       const float* w3, const float* w4, const float* w5) {
    int mat = blockIdx.y;
    int t = blockIdx.x * 256 + threadIdx.x;
    if (t >= 4096) return;
    const float* srcs[6] = {w0, w1, w2, w3, w4, w5};
    const float* W = srcs[mat];
    int nt = t >> 8, kp = (t >> 5) & 7, lane = t & 31;
    int n = nt * 8 + (lane >> 2);
    int kb = kp * 16 + (lane & 3);
    uint4 v;
    v.x = totf32(W[(kb + 0)  * 128 + n]);
    v.y = totf32(W[(kb + 4)  * 128 + n]);
    v.z = totf32(W[(kb + 8)  * 128 + n]);
    v.w = totf32(W[(kb + 12) * 128 + n]);
    g_wimg[mat * 4096 + t] = v;
}

// ---------------- GEMM layouts ----------------
#define XP    132
#define SM_B  (128 * XP * 4)        // 67584 (gemmB, 256 thr, 2 blocks/SM)
#define SM_AC (2 * 128 * XP * 4)    // 135168 (gemmAC, 512 thr, 1 block/SM)

template<int NT>
__device__ __forceinline__ void load_xT(float* sX, const float* __restrict__ x,
                                        int rowBase, int n, int tid) {
    const float4* s4 = (const float4*)x;
    #pragma unroll 4
    for (int i = tid; i < 4096; i += NT) {
        int m = i >> 5, c4 = i & 31;
        float4 v = (rowBase + m < n) ? s4[(size_t)(rowBase + m) * 32 + c4]
                                     : make_float4(0.f, 0.f, 0.f, 0.f);
        uint4 o;
        o.x = totf32(v.x); o.y = totf32(v.y); o.z = totf32(v.z); o.w = totf32(v.w);
        *(uint4*)(&sX[m * XP + c4 * 4]) = o;
    }
}

// ---- 256-thread (8 warp, 2(wn) x 4(wm)) product: 64-col slab, d[2][8][4] ----
__device__ __forceinline__ void product8(const float* sX, const uint4* __restrict__ gW,
                                         float d[2][8][4], int wm, int wn, int lane) {
    int r0a = (wm * 2 + 0) * 16 + (lane >> 2);
    int r0b = (wm * 2 + 1) * 16 + (lane >> 2);
    int kl = lane & 3;
    for (int kp = 0; kp < 8; kp++) {
        uint32_t a[2][2][4];
        #pragma unroll
        for (int s = 0; s < 2; s++) {
            int k0 = (kp * 2 + s) * 8 + kl;
            a[0][s][0] = __float_as_uint(sX[r0a * XP + k0]);
            a[0][s][1] = __float_as_uint(sX[(r0a + 8) * XP + k0]);
            a[0][s][2] = __float_as_uint(sX[r0a * XP + k0 + 4]);
            a[0][s][3] = __float_as_uint(sX[(r0a + 8) * XP + k0 + 4]);
            a[1][s][0] = __float_as_uint(sX[r0b * XP + k0]);
            a[1][s][1] = __float_as_uint(sX[(r0b + 8) * XP + k0]);
            a[1][s][2] = __float_as_uint(sX[r0b * XP + k0 + 4]);
            a[1][s][3] = __float_as_uint(sX[(r0b + 8) * XP + k0 + 4]);
        }
        #pragma unroll
        for (int j = 0; j < 8; j++) {
            uint4 b = __ldg(&gW[((wn * 8 + j) * 8 + kp) * 32 + lane]);
            mma8(d[0][j], a[0][0], b.x, b.y);
            mma8(d[1][j], a[1][0], b.x, b.y);
            mma8(d[0][j], a[0][1], b.z, b.w);
            mma8(d[1][j], a[1][1], b.z, b.w);
        }
    }
}

// ---- 512-thread (16 warp, 4m x 4n) product: 32-col slab, d[2][4][4] ----
__device__ __forceinline__ void product4(const float* sX, const uint4* __restrict__ gW,
                                         float d[2][4][4], int wm, int wn, int lane) {
    int r0a = wm * 32 + 0  + (lane >> 2);
    int r0b = wm * 32 + 16 + (lane >> 2);
    int kl = lane & 3;
    for (int kp = 0; kp < 8; kp++) {
        uint32_t a[2][2][4];
        #pragma unroll
        for (int s = 0; s < 2; s++) {
            int k0 = (kp * 2 + s) * 8 + kl;
            a[0][s][0] = __float_as_uint(sX[r0a * XP + k0]);
            a[0][s][1] = __float_as_uint(sX[(r0a + 8) * XP + k0]);
            a[0][s][2] = __float_as_uint(sX[r0a * XP + k0 + 4]);
            a[0][s][3] = __float_as_uint(sX[(r0a + 8) * XP + k0 + 4]);
            a[1][s][0] = __float_as_uint(sX[r0b * XP + k0]);
            a[1][s][1] = __float_as_uint(sX[(r0b + 8) * XP + k0]);
            a[1][s][2] = __float_as_uint(sX[r0b * XP + k0 + 4]);
            a[1][s][3] = __float_as_uint(sX[(r0b + 8) * XP + k0 + 4]);
        }
        #pragma unroll
        for (int j = 0; j < 4; j++) {
            uint4 b = __ldg(&gW[((wn * 4 + j) * 8 + kp) * 32 + lane]);
            mma8(d[0][j], a[0][0], b.x, b.y);
            mma8(d[1][j], a[1][0], b.x, b.y);
            mma8(d[0][j], a[0][1], b.z, b.w);
            mma8(d[1][j], a[1][1], b.z, b.w);
        }
    }
}

// p = sigmoid(fdst@wr + h@ur + br) * h  -> bf16 g_pb
__global__ void __launch_bounds__(256, 2) k_gemmB(const float* __restrict__ fdst,
                                                  const float* __restrict__ h,
                                                  const float* __restrict__ br, int n) {
    extern __shared__ char sm[];
    float* sX = (float*)sm;
    int tid = threadIdx.x, w = tid >> 5, lane = tid & 31;
    int wm = w >> 1, wn = w & 1;
    int rowBase = blockIdx.x * 128;

    load_xT<256>(sX, fdst, rowBase, n, tid);
    __syncthreads();

    float d[2][8][4];
    #pragma unroll
    for (int i = 0; i < 2; i++)
        #pragma unroll
        for (int j = 0; j < 8; j++)
            #pragma unroll
            for (int q = 0; q < 4; q++) d[i][j][q] = 0.f;

    product8(sX, &g_wimg[2 * 4096], d, wm, wn, lane);
    __syncthreads();
    load_xT<256>(sX, h, rowBase, n, tid);
    __syncthreads();
    product8(sX, &g_wimg[3 * 4096], d, wm, wn, lane);

    #pragma unroll
    for (int i = 0; i < 2; i++) {
        int Rl = (wm * 2 + i) * 16 + (lane >> 2);
        int R = rowBase + Rl;
        #pragma unroll
        for (int j = 0; j < 8; j++) {
            int C = wn * 64 + j * 8 + (lane & 3) * 2;
            float b0 = br[C], b1 = br[C + 1];
            if (R < n) {
                float h0 = sX[Rl * XP + C], h1 = sX[Rl * XP + C + 1];
                g_pb[(size_t)R * 64 + (C >> 1)] =
                    __floats2bfloat162_rn(sigmoidf(d[i][j][0] + b0) * h0,
                                          sigmoidf(d[i][j][1] + b1) * h1);
            }
            if (R + 8 < n) {
                float h0 = sX[(Rl + 8) * XP + C], h1 = sX[(Rl + 8) * XP + C + 1];
                g_pb[(size_t)(R + 8) * 64 + (C >> 1)] =
                    __floats2bfloat162_rn(sigmoidf(d[i][j][2] + b0) * h0,
                                          sigmoidf(d[i][j][3] + b1) * h1);
            }
        }
    }
}

// fused: z = sigmoid(fsrc@wz + s@uz + bz); ht = tanh(fsrc@w + q@u + b);
//        out = (1-z)*s + z*ht
__global__ void __launch_bounds__(512, 1) k_gemmAC(const float* __restrict__ fsrc,
                                                   const float* __restrict__ bz,
                                                   const float* __restrict__ b,
                                                   float* __restrict__ out, int n) {
    extern __shared__ char sm[];
    float* sS = (float*)sm;                    // s tile (tf32 bits), persistent
    float* sX = (float*)(sm + 128 * XP * 4);   // q tile, then fsrc tile
    int tid = threadIdx.x, w = tid >> 5, lane = tid & 31;
    int wm = w >> 2, wn = w & 3;
    int rowBase = blockIdx.x * 128;

    load_xT<512>(sS, g_s, rowBase, n, tid);
    load_xT<512>(sX, g_q, rowBase, n, tid);
    __syncthreads();

    float d1[2][4][4], d2[2][4][4];
    #pragma unroll
    for (int i = 0; i < 2; i++)
        #pragma unroll
        for (int j = 0; j < 4; j++)
            #pragma unroll
            for (int q = 0; q < 4; q++) { d1[i][j][q] = 0.f; d2[i][j][q] = 0.f; }

    product4(sS, &g_wimg[4 * 4096], d1, wm, wn, lane);   // s @ uz
    product4(sX, &g_wimg[5 * 4096], d2, wm, wn, lane);   // q @ u
    __syncthreads();
    load_xT<512>(sX, fsrc, rowBase, n, tid);
    __syncthreads();
    product4(sX, &g_wimg[0 * 4096], d1, wm, wn, lane);   // + fsrc @ wz
    product4(sX, &g_wimg[1 * 4096], d2, wm, wn, lane);   // + fsrc @ w

    #pragma unroll
    for (int i = 0; i < 2; i++) {
        int Rl = wm * 32 + i * 16 + (lane >> 2);
        int R = rowBase + Rl;
        #pragma unroll
        for (int j = 0; j < 4; j++) {
            int C = wn * 32 + j * 8 + (lane & 3) * 2;
            float bz0 = bz[C], bz1 = bz[C + 1];
            float bb0 = b[C],  bb1 = b[C + 1];
            if (R < n) {
                float s0 = sS[Rl * XP + C], s1 = sS[Rl * XP + C + 1];
                float z0 = sigmoidf(d1[i][j][0] + bz0);
                float z1 = sigmoidf(d1[i][j][1] + bz1);
                float t0 = tanh_fast(d2[i][j][0] + bb0);
                float t1 = tanh_fast(d2[i][j][1] + bb1);
                *(float2*)(out + (size_t)R * 128 + C) =
                    make_float2((1.f - z0) * s0 + z0 * t0,
                                (1.f - z1) * s1 + z1 * t1);
            }
            if (R + 8 < n) {
                float s0 = sS[(Rl + 8) * XP + C], s1 = sS[(Rl + 8) * XP + C + 1];
                float z0 = sigmoidf(d1[i][j][2] + bz0);
                float z1 = sigmoidf(d1[i][j][3] + bz1);
                float t0 = tanh_fast(d2[i][j][2] + bb0);
                float t1 = tanh_fast(d2[i][j][3] + bb1);
                *(float2*)(out + (size_t)(R + 8) * 128 + C) =
                    make_float2((1.f - z0) * s0 + z0 * t0,
                                (1.f - z1) * s1 + z1 * t1);
            }
        }
    }
}

// ---------------- launch ----------------
extern "C" void kernel_launch(void* const* d_in, const int* in_sizes, int n_in,
                              void* d_out, int out_size)
{
    const float* h    = (const float*)d_in[0];
    const float* fsrc = (const float*)d_in[1];
    const float* fdst = (const float*)d_in[2];
    const int*   src  = (const int*)d_in[3];
    const int*   dst  = (const int*)d_in[4];
    const float* wz   = (const float*)d_in[5];
    const float* uz   = (const float*)d_in[6];
    const float* bz   = (const float*)d_in[7];
    const float* wr   = (const float*)d_in[8];
    const float* ur   = (const float*)d_in[9];
    const float* br   = (const float*)d_in[10];
    const float* w    = (const float*)d_in[11];
    const float* u    = (const float*)d_in[12];
    const float* b    = (const float*)d_in[13];
    float* out = (float*)d_out;

    int n = in_sizes[0] / 128;
    int e = in_sizes[3];
    if (n > NMAX || e > EMAX) return;

    static cudaStream_t sB = nullptr;
    static cudaEvent_t evF = nullptr, evCSR = nullptr, evQ = nullptr;
    if (!sB) {
        cudaStreamCreateWithFlags(&sB, cudaStreamNonBlocking);
        cudaEventCreateWithFlags(&evF, cudaEventDisableTiming);
        cudaEventCreateWithFlags(&evCSR, cudaEventDisableTiming);
        cudaEventCreateWithFlags(&evQ, cudaEventDisableTiming);
    }

    cudaFuncSetAttribute(k_gemmB,  cudaFuncAttributeMaxDynamicSharedMemorySize, SM_B);
    cudaFuncSetAttribute(k_gemmAC, cudaFuncAttributeMaxDynamicSharedMemorySize, SM_AC);

    int gemmBlocks = (n + 127) / 128;
    int nb = (n + 1023) / 1024;

    // fork: branch B (prep + gemmB) runs concurrently with the CSR chain
    cudaEventRecord(evF, 0);
    cudaStreamWaitEvent(sB, evF, 0);
    k_prep<<<dim3(16, 6), 256, 0, sB>>>(wz, w, wr, ur, uz, u);
    k_gemmB<<<gemmBlocks, 256, SM_B, sB>>>(fdst, h, br, n);

    // branch A: CSR chain on main stream
    k_zero<<<(n + 255) / 256, 256>>>(n);
    k_hist<<<(e + 255) / 256, 256>>>(dst, e);
    k_part<<<nb, 1024>>>(n);
    k_scanb<<<1, 128>>>(nb);
    k_add<<<(n + 1023) / 1024, 1024>>>(n, e);
    k_scatter<<<(e + 255) / 256, 256>>>(src, dst, e);
    cudaEventRecord(evCSR, 0);

    // s-reduce needs only CSR + h: run immediately on main stream
    k_reduceS<<<(n + 7) / 8, 256>>>(h, n);

    // q-reduce needs CSR + gemmB output: run on stream B
    cudaStreamWaitEvent(sB, evCSR, 0);
    k_reduceQ<<<(n + 7) / 8, 256, 0, sB>>>(n);
    cudaEventRecord(evQ, sB);

    // join, then fused gate GEMM
    cudaStreamWaitEvent(0, evQ, 0);
    k_gemmAC<<<gemmBlocks, 512, SM_AC>>>(fsrc, bz, b, out, n);
}

// round 11
// speedup vs baseline: 5.6340x; 1.0010x over previous
#include <cuda_runtime.h>
#include <cuda_bf16.h>
#include <cuda_fp16.h>
#include <cstdint>

#define NMAX 100000
#define EMAX 1600000

// ---------------- scratch ----------------
__device__ __nv_bfloat162 g_pb[NMAX * 64];   // p compressed to bf16 (gather operand)
__device__ __half2 g_hh[NMAX * 64];          // h compressed to fp16 (gather operand)
__device__ float g_s [NMAX * 128];
__device__ float g_q [NMAX * 128];
__device__ int   g_cnt[NMAX];
__device__ int   g_off[NMAX + 1];
__device__ int   g_cur[NMAX];
__device__ int   g_perm[EMAX];
__device__ int   g_bsum[128];
__device__ int   g_bpre[128];
__device__ uint4 g_wimg[6 * 4096];   // 6 weight images, 64KB each, B-fragment order

__device__ __forceinline__ float sigmoidf(float x) { return 1.0f / (1.0f + __expf(-x)); }
__device__ __forceinline__ float tanh_fast(float x) {
    return __fdividef(2.0f, 1.0f + __expf(-2.0f * x)) - 1.0f;
}
__device__ __forceinline__ uint32_t totf32(float f) {
    uint32_t r; asm("cvt.rna.tf32.f32 %0,%1;" : "=r"(r) : "f"(f)); return r;
}

// ---------------- mma.sync m16n8k8 tf32 ----------------
__device__ __forceinline__ void mma8(float* d, const uint32_t* a, uint32_t b0, uint32_t b1) {
    asm("mma.sync.aligned.m16n8k8.row.col.f32.tf32.tf32.f32 "
        "{%0,%1,%2,%3},{%4,%5,%6,%7},{%8,%9},{%0,%1,%2,%3};"
        : "+f"(d[0]), "+f"(d[1]), "+f"(d[2]), "+f"(d[3])
        : "r"(a[0]), "r"(a[1]), "r"(a[2]), "r"(a[3]), "r"(b0), "r"(b1));
}

// ---------------- h -> fp16 compression ----------------
__global__ void k_hcomp(const float* __restrict__ h, int n) {
    int i = blockIdx.x * blockDim.x + threadIdx.x;   // one float4 -> one uint2
    if (i >= n * 32) return;
    float4 v = ((const float4*)h)[i];
    __half2 lo = __floats2half2_rn(v.x, v.y);
    __half2 hi = __floats2half2_rn(v.z, v.w);
    g_hh[i * 2 + 0] = lo;
    g_hh[i * 2 + 1] = hi;
}

// ---------------- CSR build ----------------
__global__ void k_zero(int n) {
    int i = blockIdx.x * blockDim.x + threadIdx.x;
    if (i < n) g_cnt[i] = 0;
}
__global__ void k_hist(const int* __restrict__ dst, int e) {
    int i = blockIdx.x * blockDim.x + threadIdx.x;
    if (i < e) atomicAdd(&g_cnt[dst[i]], 1);
}

__global__ void k_part(int n) {
    __shared__ int sm[1024];
    int b = blockIdx.x, t = threadIdx.x;
    int idx = b * 1024 + t;
    int v = (idx < n) ? g_cnt[idx] : 0;
    sm[t] = v;
    __syncthreads();
    #pragma unroll
    for (int off = 1; off < 1024; off <<= 1) {
        int x = (t >= off) ? sm[t - off] : 0;
        __syncthreads();
        sm[t] += x;
        __syncthreads();
    }
    if (idx < n) g_off[idx] = sm[t] - v;
    if (t == 1023) g_bsum[b] = sm[t];
}

__global__ void k_scanb(int nb) {
    __shared__ int sm[128];
    int t = threadIdx.x;
    int v = (t < nb) ? g_bsum[t] : 0;
    sm[t] = v;
    __syncthreads();
    #pragma unroll
    for (int off = 1; off < 128; off <<= 1) {
        int x = (t >= off) ? sm[t - off] : 0;
        __syncthreads();
        sm[t] += x;
        __syncthreads();
    }
    if (t < nb) g_bpre[t] = sm[t] - v;
}

__global__ void k_add(int n, int e) {
    int idx = blockIdx.x * blockDim.x + threadIdx.x;
    if (idx < n) {
        int o = g_off[idx] + g_bpre[idx >> 10];
        g_off[idx] = o;
        g_cur[idx] = o;
    }
    if (idx == 0) g_off[n] = e;
}

__global__ void k_scatter(const int* __restrict__ src, const int* __restrict__ dst, int e) {
    int i = blockIdx.x * blockDim.x + threadIdx.x;
    if (i < e) {
        int d = dst[i];
        int pos = atomicAdd(&g_cur[d], 1);
        g_perm[pos] = src[i];
    }
}

// ---------------- segment reduce, split: s (fp16 h) / q (bf16 p) ----------------
__global__ void k_reduceS(int n) {
    int gw = (blockIdx.x * blockDim.x + threadIdx.x) >> 5;
    int lane = threadIdx.x & 31;
    if (gw >= n) return;
    int i0 = g_off[gw], i1 = g_off[gw + 1];
    const uint2* hh = (const uint2*)g_hh;   // lane -> cols 4l..4l+3
    float4 sa = make_float4(0.f, 0.f, 0.f, 0.f);
    int i = i0;
    for (; i + 3 < i1; i += 4) {
        int u0 = g_perm[i], u1 = g_perm[i + 1], u2 = g_perm[i + 2], u3 = g_perm[i + 3];
        uint2 b0 = hh[u0 * 32 + lane];
        uint2 b1 = hh[u1 * 32 + lane];
        uint2 b2 = hh[u2 * 32 + lane];
        uint2 b3 = hh[u3 * 32 + lane];
        float2 f0 = __half22float2(*(__half2*)&b0.x);
        float2 g0 = __half22float2(*(__half2*)&b0.y);
        float2 f1 = __half22float2(*(__half2*)&b1.x);
        float2 g1 = __half22float2(*(__half2*)&b1.y);
        float2 f2 = __half22float2(*(__half2*)&b2.x);
        float2 g2 = __half22float2(*(__half2*)&b2.y);
        float2 f3 = __half22float2(*(__half2*)&b3.x);
        float2 g3 = __half22float2(*(__half2*)&b3.y);
        sa.x += (f0.x + f1.x) + (f2.x + f3.x);
        sa.y += (f0.y + f1.y) + (f2.y + f3.y);
        sa.z += (g0.x + g1.x) + (g2.x + g3.x);
        sa.w += (g0.y + g1.y) + (g2.y + g3.y);
    }
    for (; i < i1; i++) {
        int u0 = g_perm[i];
        uint2 b0 = hh[u0 * 32 + lane];
        float2 f0 = __half22float2(*(__half2*)&b0.x);
        float2 g0 = __half22float2(*(__half2*)&b0.y);
        sa.x += f0.x; sa.y += f0.y; sa.z += g0.x; sa.w += g0.y;
    }
    ((float4*)g_s)[gw * 32 + lane] = sa;
}

__global__ void k_reduceQ(int n) {
    int gw = (blockIdx.x * blockDim.x + threadIdx.x) >> 5;
    int lane = threadIdx.x & 31;
    if (gw >= n) return;
    int i0 = g_off[gw], i1 = g_off[gw + 1];
    const uint2* pb = (const uint2*)g_pb;   // lane -> cols 4l..4l+3
    float4 qa = make_float4(0.f, 0.f, 0.f, 0.f);
    int i = i0;
    for (; i + 3 < i1; i += 4) {
        int u0 = g_perm[i], u1 = g_perm[i + 1], u2 = g_perm[i + 2], u3 = g_perm[i + 3];
        uint2 b0 = pb[u0 * 32 + lane];
        uint2 b1 = pb[u1 * 32 + lane];
        uint2 b2 = pb[u2 * 32 + lane];
        uint2 b3 = pb[u3 * 32 + lane];
        float2 f0 = __bfloat1622float2(*(__nv_bfloat162*)&b0.x);
        float2 g0 = __bfloat1622float2(*(__nv_bfloat162*)&b0.y);
        float2 f1 = __bfloat1622float2(*(__nv_bfloat162*)&b1.x);
        float2 g1 = __bfloat1622float2(*(__nv_bfloat162*)&b1.y);
        float2 f2 = __bfloat1622float2(*(__nv_bfloat162*)&b2.x);
        float2 g2 = __bfloat1622float2(*(__nv_bfloat162*)&b2.y);
        float2 f3 = __bfloat1622float2(*(__nv_bfloat162*)&b3.x);
        float2 g3 = __bfloat1622float2(*(__nv_bfloat162*)&b3.y);
        qa.x += (f0.x + f1.x) + (f2.x + f3.x);
        qa.y += (f0.y + f1.y) + (f2.y + f3.y);
        qa.z += (g0.x + g1.x) + (g2.x + g3.x);
        qa.w += (g0.y + g1.y) + (g2.y + g3.y);
    }
    for (; i < i1; i++) {
        int u0 = g_perm[i];
        uint2 b0 = pb[u0 * 32 + lane];
        float2 f0 = __bfloat1622float2(*(__nv_bfloat162*)&b0.x);
        float2 g0 = __bfloat1622float2(*(__nv_bfloat162*)&b0.y);
        qa.x += f0.x; qa.y += f0.y; qa.z += g0.x; qa.w += g0.y;
    }
    ((float4*)g_q)[gw * 32 + lane] = qa;
}

// ---------------- weight fragment image prep ----------------
__global__ void k_prep(const float* w0, const float* w1, const float* w2,
                       const float* w3, const float* w4, const float* w5) {
    int mat = blockIdx.y;
    int t = blockIdx.x * 256 + threadIdx.x;
    if (t >= 4096) return;
    const float* srcs[6] = {w0, w1, w2, w3, w4, w5};
    const float* W = srcs[mat];
    int nt = t >> 8, kp = (t >> 5) & 7, lane = t & 31;
    int n = nt * 8 + (lane >> 2);
    int kb = kp * 16 + (lane & 3);
    uint4 v;
    v.x = totf32(W[(kb + 0)  * 128 + n]);
    v.y = totf32(W[(kb + 4)  * 128 + n]);
    v.z = totf32(W[(kb + 8)  * 128 + n]);
    v.w = totf32(W[(kb + 12) * 128 + n]);
    g_wimg[mat * 4096 + t] = v;
}

// ---------------- GEMM layouts ----------------
#define XP    132
#define SM_B  (128 * XP * 4)        // 67584 (gemmB, 256 thr, 2 blocks/SM)
#define SM_AC (2 * 128 * XP * 4)    // 135168 (gemmAC, 512 thr, 1 block/SM)

template<int NT>
__device__ __forceinline__ void load_xT(float* sX, const float* __restrict__ x,
                                        int rowBase, int n, int tid) {
    const float4* s4 = (const float4*)x;
    #pragma unroll 4
    for (int i = tid; i < 4096; i += NT) {
        int m = i >> 5, c4 = i & 31;
        float4 v = (rowBase + m < n) ? s4[(size_t)(rowBase + m) * 32 + c4]
                                     : make_float4(0.f, 0.f, 0.f, 0.f);
        uint4 o;
        o.x = totf32(v.x); o.y = totf32(v.y); o.z = totf32(v.z); o.w = totf32(v.w);
        *(uint4*)(&sX[m * XP + c4 * 4]) = o;
    }
}

// ---- 256-thread (8 warp, 2(wn) x 4(wm)) product: 64-col slab, d[2][8][4] ----
__device__ __forceinline__ void product8(const float* sX, const uint4* __restrict__ gW,
                                         float d[2][8][4], int wm, int wn, int lane) {
    int r0a = (wm * 2 + 0) * 16 + (lane >> 2);
    int r0b = (wm * 2 + 1) * 16 + (lane >> 2);
    int kl = lane & 3;
    for (int kp = 0; kp < 8; kp++) {
        uint32_t a[2][2][4];
        #pragma unroll
        for (int s = 0; s < 2; s++) {
            int k0 = (kp * 2 + s) * 8 + kl;
            a[0][s][0] = __float_as_uint(sX[r0a * XP + k0]);
            a[0][s][1] = __float_as_uint(sX[(r0a + 8) * XP + k0]);
            a[0][s][2] = __float_as_uint(sX[r0a * XP + k0 + 4]);
            a[0][s][3] = __float_as_uint(sX[(r0a + 8) * XP + k0 + 4]);
            a[1][s][0] = __float_as_uint(sX[r0b * XP + k0]);
            a[1][s][1] = __float_as_uint(sX[(r0b + 8) * XP + k0]);
            a[1][s][2] = __float_as_uint(sX[r0b * XP + k0 + 4]);
            a[1][s][3] = __float_as_uint(sX[(r0b + 8) * XP + k0 + 4]);
        }
        #pragma unroll
        for (int j = 0; j < 8; j++) {
            uint4 b = __ldg(&gW[((wn * 8 + j) * 8 + kp) * 32 + lane]);
            mma8(d[0][j], a[0][0], b.x, b.y);
            mma8(d[1][j], a[1][0], b.x, b.y);
            mma8(d[0][j], a[0][1], b.z, b.w);
            mma8(d[1][j], a[1][1], b.z, b.w);
        }
    }
}

// ---- 512-thread (16 warp, 4m x 4n) product: 32-col slab, d[2][4][4] ----
__device__ __forceinline__ void product4(const float* sX, const uint4* __restrict__ gW,
                                         float d[2][4][4], int wm, int wn, int lane) {
    int r0a = wm * 32 + 0  + (lane >> 2);
    int r0b = wm * 32 + 16 + (lane >> 2);
    int kl = lane & 3;
    for (int kp = 0; kp < 8; kp++) {
        uint32_t a[2][2][4];
        #pragma unroll
        for (int s = 0; s < 2; s++) {
            int k0 = (kp * 2 + s) * 8 + kl;
            a[0][s][0] = __float_as_uint(sX[r0a * XP + k0]);
            a[0][s][1] = __float_as_uint(sX[(r0a + 8) * XP + k0]);
            a[0][s][2] = __float_as_uint(sX[r0a * XP + k0 + 4]);
            a[0][s][3] = __float_as_uint(sX[(r0a + 8) * XP + k0 + 4]);
            a[1][s][0] = __float_as_uint(sX[r0b * XP + k0]);
            a[1][s][1] = __float_as_uint(sX[(r0b + 8) * XP + k0]);
            a[1][s][2] = __float_as_uint(sX[r0b * XP + k0 + 4]);
            a[1][s][3] = __float_as_uint(sX[(r0b + 8) * XP + k0 + 4]);
        }
        #pragma unroll
        for (int j = 0; j < 4; j++) {
            uint4 b = __ldg(&gW[((wn * 4 + j) * 8 + kp) * 32 + lane]);
            mma8(d[0][j], a[0][0], b.x, b.y);
            mma8(d[1][j], a[1][0], b.x, b.y);
            mma8(d[0][j], a[0][1], b.z, b.w);
            mma8(d[1][j], a[1][1], b.z, b.w);
        }
    }
}

// p = sigmoid(fdst@wr + h@ur + br) * h  -> bf16 g_pb
__global__ void __launch_bounds__(256, 2) k_gemmB(const float* __restrict__ fdst,
                                                  const float* __restrict__ h,
                                                  const float* __restrict__ br, int n) {
    extern __shared__ char sm[];
    float* sX = (float*)sm;
    int tid = threadIdx.x, w = tid >> 5, lane = tid & 31;
    int wm = w >> 1, wn = w & 1;
    int rowBase = blockIdx.x * 128;

    load_xT<256>(sX, fdst, rowBase, n, tid);
    __syncthreads();

    float d[2][8][4];
    #pragma unroll
    for (int i = 0; i < 2; i++)
        #pragma unroll
        for (int j = 0; j < 8; j++)
            #pragma unroll
            for (int q = 0; q < 4; q++) d[i][j][q] = 0.f;

    product8(sX, &g_wimg[2 * 4096], d, wm, wn, lane);
    __syncthreads();
    load_xT<256>(sX, h, rowBase, n, tid);
    __syncthreads();
    product8(sX, &g_wimg[3 * 4096], d, wm, wn, lane);

    #pragma unroll
    for (int i = 0; i < 2; i++) {
        int Rl = (wm * 2 + i) * 16 + (lane >> 2);
        int R = rowBase + Rl;
        #pragma unroll
        for (int j = 0; j < 8; j++) {
            int C = wn * 64 + j * 8 + (lane & 3) * 2;
            float b0 = br[C], b1 = br[C + 1];
            if (R < n) {
                float h0 = sX[Rl * XP + C], h1 = sX[Rl * XP + C + 1];
                g_pb[(size_t)R * 64 + (C >> 1)] =
                    __floats2bfloat162_rn(sigmoidf(d[i][j][0] + b0) * h0,
                                          sigmoidf(d[i][j][1] + b1) * h1);
            }
            if (R + 8 < n) {
                float h0 = sX[(Rl + 8) * XP + C], h1 = sX[(Rl + 8) * XP + C + 1];
                g_pb[(size_t)(R + 8) * 64 + (C >> 1)] =
                    __floats2bfloat162_rn(sigmoidf(d[i][j][2] + b0) * h0,
                                          sigmoidf(d[i][j][3] + b1) * h1);
            }
        }
    }
}

// fused: z = sigmoid(fsrc@wz + s@uz + bz); ht = tanh(fsrc@w + q@u + b);
//        out = (1-z)*s + z*ht
__global__ void __launch_bounds__(512, 1) k_gemmAC(const float* __restrict__ fsrc,
                                                   const float* __restrict__ bz,
                                                   const float* __restrict__ b,
                                                   float* __restrict__ out, int n) {
    extern __shared__ char sm[];
    float* sS = (float*)sm;                    // s tile (tf32 bits), persistent
    float* sX = (float*)(sm + 128 * XP * 4);   // q tile, then fsrc tile
    int tid = threadIdx.x, w = tid >> 5, lane = tid & 31;
    int wm = w >> 2, wn = w & 3;
    int rowBase = blockIdx.x * 128;

    load_xT<512>(sS, g_s, rowBase, n, tid);
    load_xT<512>(sX, g_q, rowBase, n, tid);
    __syncthreads();

    float d1[2][4][4], d2[2][4][4];
    #pragma unroll
    for (int i = 0; i < 2; i++)
        #pragma unroll
        for (int j = 0; j < 4; j++)
            #pragma unroll
            for (int q = 0; q < 4; q++) { d1[i][j][q] = 0.f; d2[i][j][q] = 0.f; }

    product4(sS, &g_wimg[4 * 4096], d1, wm, wn, lane);   // s @ uz
    product4(sX, &g_wimg[5 * 4096], d2, wm, wn, lane);   // q @ u
    __syncthreads();
    load_xT<512>(sX, fsrc, rowBase, n, tid);
    __syncthreads();
    product4(sX, &g_wimg[0 * 4096], d1, wm, wn, lane);   // + fsrc @ wz
    product4(sX, &g_wimg[1 * 4096], d2, wm, wn, lane);   // + fsrc @ w

    #pragma unroll
    for (int i = 0; i < 2; i++) {
        int Rl = wm * 32 + i * 16 + (lane >> 2);
        int R = rowBase + Rl;
        #pragma unroll
        for (int j = 0; j < 4; j++) {
            int C = wn * 32 + j * 8 + (lane & 3) * 2;
            float bz0 = bz[C], bz1 = bz[C + 1];
            float bb0 = b[C],  bb1 = b[C + 1];
            if (R < n) {
                float s0 = sS[Rl * XP + C], s1 = sS[Rl * XP + C + 1];
                float z0 = sigmoidf(d1[i][j][0] + bz0);
                float z1 = sigmoidf(d1[i][j][1] + bz1);
                float t0 = tanh_fast(d2[i][j][0] + bb0);
                float t1 = tanh_fast(d2[i][j][1] + bb1);
                *(float2*)(out + (size_t)R * 128 + C) =
                    make_float2((1.f - z0) * s0 + z0 * t0,
                                (1.f - z1) * s1 + z1 * t1);
            }
            if (R + 8 < n) {
                float s0 = sS[(Rl + 8) * XP + C], s1 = sS[(Rl + 8) * XP + C + 1];
                float z0 = sigmoidf(d1[i][j][2] + bz0);
                float z1 = sigmoidf(d1[i][j][3] + bz1);
                float t0 = tanh_fast(d2[i][j][2] + bb0);
                float t1 = tanh_fast(d2[i][j][3] + bb1);
                *(float2*)(out + (size_t)(R + 8) * 128 + C) =
                    make_float2((1.f - z0) * s0 + z0 * t0,
                                (1.f - z1) * s1 + z1 * t1);
            }
        }
    }
}

// ---------------- launch ----------------
extern "C" void kernel_launch(void* const* d_in, const int* in_sizes, int n_in,
                              void* d_out, int out_size)
{
    const float* h    = (const float*)d_in[0];
    const float* fsrc = (const float*)d_in[1];
    const float* fdst = (const float*)d_in[2];
    const int*   src  = (const int*)d_in[3];
    const int*   dst  = (const int*)d_in[4];
    const float* wz   = (const float*)d_in[5];
    const float* uz   = (const float*)d_in[6];
    const float* bz   = (const float*)d_in[7];
    const float* wr   = (const float*)d_in[8];
    const float* ur   = (const float*)d_in[9];
    const float* br   = (const float*)d_in[10];
    const float* w    = (const float*)d_in[11];
    const float* u    = (const float*)d_in[12];
    const float* b    = (const float*)d_in[13];
    float* out = (float*)d_out;

    int n = in_sizes[0] / 128;
    int e = in_sizes[3];
    if (n > NMAX || e > EMAX) return;

    static cudaStream_t sB = nullptr;
    static cudaEvent_t evF = nullptr, evCSR = nullptr, evQ = nullptr;
    if (!sB) {
        cudaStreamCreateWithFlags(&sB, cudaStreamNonBlocking);
        cudaEventCreateWithFlags(&evF, cudaEventDisableTiming);
        cudaEventCreateWithFlags(&evCSR, cudaEventDisableTiming);
        cudaEventCreateWithFlags(&evQ, cudaEventDisableTiming);
    }

    cudaFuncSetAttribute(k_gemmB,  cudaFuncAttributeMaxDynamicSharedMemorySize, SM_B);
    cudaFuncSetAttribute(k_gemmAC, cudaFuncAttributeMaxDynamicSharedMemorySize, SM_AC);

    int gemmBlocks = (n + 127) / 128;
    int nb = (n + 1023) / 1024;

    // fork: branch B (prep + gemmB) runs concurrently with the CSR chain
    cudaEventRecord(evF, 0);
    cudaStreamWaitEvent(sB, evF, 0);
    k_prep<<<dim3(16, 6), 256, 0, sB>>>(wz, w, wr, ur, uz, u);
    k_gemmB<<<gemmBlocks, 256, SM_B, sB>>>(fdst, h, br, n);

    // branch A: h compression + CSR chain on main stream
    k_hcomp<<<(n * 32 + 255) / 256, 256>>>(h, n);
    k_zero<<<(n + 255) / 256, 256>>>(n);
    k_hist<<<(e + 255) / 256, 256>>>(dst, e);
    k_part<<<nb, 1024>>>(n);
    k_scanb<<<1, 128>>>(nb);
    k_add<<<(n + 1023) / 1024, 1024>>>(n, e);
    k_scatter<<<(e + 255) / 256, 256>>>(src, dst, e);
    cudaEventRecord(evCSR, 0);

    // s-reduce needs only CSR + compressed h: run immediately on main stream
    k_reduceS<<<(n + 7) / 8, 256>>>(n);

    // q-reduce needs CSR + gemmB output: run on stream B
    cudaStreamWaitEvent(sB, evCSR, 0);
    k_reduceQ<<<(n + 7) / 8, 256, 0, sB>>>(n);
    cudaEventRecord(evQ, sB);

    // join, then fused gate GEMM
    cudaStreamWaitEvent(0, evQ, 0);
    k_gemmAC<<<gemmBlocks, 512, SM_AC>>>(fsrc, bz, b, out, n);
}